// round 15
// baseline (speedup 1.0000x reference)
#include <cuda_runtime.h>
#include <cuda_bf16.h>
#include <math.h>

// ---------------- problem constants ----------------
#define NB 16      // batch
#define NT 4096    // tokens
#define HH 1024    // hidden
#define NS 16      // segments
#define NP 6       // plan slots
#define NHEAD 8
#define DHD 128    // head dim
#define PLAN_ELEMS (NB*NP*HH)   // 98304

// ---------------- device scratch (static, no allocs) ----------------
__device__ int   g_bounds[NB*(NS+1)];
__device__ float g_seg0[NB*NS*HH];
__device__ float g_qkv[NB*NS*3*HH];
__device__ float g_seg1[NB*NS*HH];
__device__ float g_logits[NB*NS];
__device__ float g_sal[NB*NS];
__device__ float g_qh[NP*HH];
__device__ float g_kv[NB*NS*2*HH];
__device__ float g_plan[NB*NP*HH];
__device__ float g_qkvr[NB*NP*3*HH];
__device__ float g_part[8*1024*1024];          // split-K partials (32MB); qh uses +7M
__device__ float g_entpart[NB];
__device__ float g_redpart[NB];
__device__ int   g_red_cnt;
__device__ int   g_tilecnt[512];               // per-tile arrival counters (self-resetting)

// bf16 [hi(K)|lo(K)] operand buffers
__device__ __nv_bfloat16 g_bf_seg0[256*2048];
__device__ __nv_bfloat16 g_bf_o   [256*2048];
__device__ __nv_bfloat16 g_bf_seg1[256*2048];
__device__ __nv_bfloat16 g_bf_wseg[256*2048];
__device__ __nv_bfloat16 g_bf_pq  [NP*2048];
__device__ __nv_bfloat16 g_bf_o2  [96*2048];
__device__ __nv_bfloat16 g_bf_y   [96*2048];
__device__ __nv_bfloat16 g_bf_o3  [96*2048];
__device__ __nv_bfloat16 g_bf_ffn [96*8192];
__device__ __nv_bfloat16 g_wbf[69206016];      // all weights hi|lo (138MB)

// weight offsets into g_wbf (bf16 elems)
#define WOFF_SAIN   0LL
#define WOFF_SAOUT  6291456LL
#define WOFF_SAL1   8388608LL
#define WOFF_QAIN   10485760LL
#define WOFF_QAOUT  16777216LL
#define WOFF_RIN    18874368LL
#define WOFF_ROUT   31457280LL
#define WOFF_RW1    35651584LL
#define WOFF_RW2    52428800LL

// ---------------- helpers ----------------
__device__ __forceinline__ unsigned smem_u32(const void* p) {
    unsigned a;
    asm("{ .reg .u64 t; cvta.to.shared.u64 t, %1; cvt.u32.u64 %0, t; }" : "=r"(a) : "l"(p));
    return a;
}
__device__ __forceinline__ unsigned pack_pair(float f0, float f1, bool lo) {
    if (lo) {
        f0 = f0 - __bfloat162float(__float2bfloat16(f0));
        f1 = f1 - __bfloat162float(__float2bfloat16(f1));
    }
    __nv_bfloat162 p = __floats2bfloat162_rn(f0, f1);
    return *reinterpret_cast<unsigned*>(&p);
}
__device__ __forceinline__ void cp16(unsigned dst, const void* src, int sz) {
    asm volatile("cp.async.ca.shared.global [%0], [%1], 16, %2;"
                 :: "r"(dst), "l"(src), "r"(sz));
}
__device__ __forceinline__ void whl(__nv_bfloat16* t, size_t rowbase, int K, int k, float v) {
    __nv_bfloat16 h = __float2bfloat16(v);
    __nv_bfloat16 l = __float2bfloat16(v - __bfloat162float(h));
    t[rowbase + k] = h;
    t[rowbase + K + k] = l;
}
__device__ __forceinline__ void whl4(__nv_bfloat16* t, size_t rowbase, int N, int col, float4 v) {
    unsigned h0 = pack_pair(v.x, v.y, false), h1 = pack_pair(v.z, v.w, false);
    unsigned l0 = pack_pair(v.x, v.y, true),  l1 = pack_pair(v.z, v.w, true);
    __nv_bfloat16* tr = t + rowbase + col;
    *(uint2*)tr       = make_uint2(h0, h1);
    *(uint2*)(tr + N) = make_uint2(l0, l1);
}
__device__ __forceinline__ float gelu_f(float v) {
    return 0.5f * v * (1.f + erff(v * 0.70710678118654752f));
}

// ---------------- weight conversion (all tensors, one launch) ----------------
struct CvtTab {
    const float* src[10];
    __nv_bfloat16* dst[10];
    int n[10];
    int logK[10];
};
__global__ void convert_kernel(CvtTab tab) {
    int tsel = blockIdx.y;
    const float* s = tab.src[tsel];
    __nv_bfloat16* d = tab.dst[tsel];
    long long n = tab.n[tsel];
    int logK = tab.logK[tsel];
    int K = 1 << logK;
    long long stride = (long long)gridDim.x * blockDim.x * 4;
    for (long long idx = ((long long)blockIdx.x * blockDim.x + threadIdx.x) * 4;
         idx < n; idx += stride) {
        float4 v = *(const float4*)(s + idx);
        int k = (int)(idx & (K - 1));
        long long row = idx >> logK;
        __nv_bfloat16* dr = d + row * (2LL * K) + k;
        unsigned h0 = pack_pair(v.x, v.y, false), h1 = pack_pair(v.z, v.w, false);
        unsigned l0 = pack_pair(v.x, v.y, true),  l1 = pack_pair(v.z, v.w, true);
        *(uint2*)dr       = make_uint2(h0, h1);
        *(uint2*)(dr + K) = make_uint2(l0, l1);
    }
}

// ---------------- lengths + segment bounds ----------------
__global__ void lengths_kernel(const int* __restrict__ mask) {
    int b = blockIdx.x;
    __shared__ int red[256];
    int t = threadIdx.x;
    int s = 0;
    for (int i = t; i < NT; i += 256) s += mask[b*NT + i];
    red[t] = s; __syncthreads();
    for (int o = 128; o > 0; o >>= 1) { if (t < o) red[t] += red[t+o]; __syncthreads(); }
    if (t == 0) {
        int L = red[0];
        for (int k = 0; k <= NS; k++) g_bounds[b*(NS+1) + k] = (k * L) / NS;
    }
}

// ---------------- fused segment pooling (single kernel, 4-row unrolled) ----------------
__global__ void segpool_kernel(const float* __restrict__ ts) {
    int seg = blockIdx.x;                 // 0..255
    int b = seg >> 4, s = seg & 15;
    int lo = g_bounds[b*(NS+1) + s], hi = g_bounds[b*(NS+1) + s + 1];
    int cnt = hi - lo;
    int t = threadIdx.x;                  // 256 threads, 4 cols each
    const float* base = ts + (size_t)b * NT * HH + t * 4;
    float4 a0 = make_float4(0.f,0.f,0.f,0.f), a1 = a0, a2 = a0, a3 = a0;
    int r = lo;
    for (; r + 4 <= hi; r += 4) {
        float4 v0 = *(const float4*)(base + (size_t)(r+0) * HH);
        float4 v1 = *(const float4*)(base + (size_t)(r+1) * HH);
        float4 v2 = *(const float4*)(base + (size_t)(r+2) * HH);
        float4 v3 = *(const float4*)(base + (size_t)(r+3) * HH);
        a0.x += v0.x; a0.y += v0.y; a0.z += v0.z; a0.w += v0.w;
        a1.x += v1.x; a1.y += v1.y; a1.z += v1.z; a1.w += v1.w;
        a2.x += v2.x; a2.y += v2.y; a2.z += v2.z; a2.w += v2.w;
        a3.x += v3.x; a3.y += v3.y; a3.z += v3.z; a3.w += v3.w;
    }
    for (; r < hi; r++) {
        float4 v = *(const float4*)(base + (size_t)r * HH);
        a0.x += v.x; a0.y += v.y; a0.z += v.z; a0.w += v.w;
    }
    float inv = 1.f / fmaxf((float)cnt, 1.f);
    float4 v;
    v.x = (a0.x + a1.x + a2.x + a3.x) * inv;
    v.y = (a0.y + a1.y + a2.y + a3.y) * inv;
    v.z = (a0.z + a1.z + a2.z + a3.z) * inv;
    v.w = (a0.w + a1.w + a2.w + a3.w) * inv;
    *(float4*)&g_seg0[(size_t)seg * HH + t*4] = v;
    whl4(g_bf_seg0, (size_t)seg * 2048, 1024, t*4, v);
}

// ---------------- bf16 split-K GEMM (compensated, fragment-reuse, cp.async 2-stage) ----------------
// D = A_hi*W_hi + A_lo*W_hi + A_hi*W_lo.  A,W stored [rows, 2K] = [hi(K)|lo(K)].
// 128x128 tile, BK=32, 256 thr, 8 warps 64x32. Optional fused last-block epilogue:
// the last split-K block for a tile reduces all slices (fixed z order: deterministic),
// applies bias/gelu/res, writes fp32/out2/bf16 outputs, resets its counter.
#define SA 40   // padded smem row stride (bf16) => 80B
#define MATB (128*SA*2)        // 10240 bytes per tile
#define STGB (4*MATB)          // 40960 bytes per stage

__global__ void __launch_bounds__(256) gemm_bf16_kernel(
    const __nv_bfloat16* __restrict__ A, const __nv_bfloat16* __restrict__ W,
    float* __restrict__ P, int M, int N, int K, int kslices,
    int fuse, const float* __restrict__ bias, const float* __restrict__ res,
    float* __restrict__ out, float* __restrict__ out2, int out2_lim,
    __nv_bfloat16* __restrict__ tout, int gelu, int* __restrict__ cnt)
{
    extern __shared__ __align__(16) unsigned char smem[];
    int tid = threadIdx.x, wid = tid >> 5, lane = tid & 31;
    int m0 = blockIdx.x * 128, n0 = blockIdx.y * 128;
    int K2 = 2 * K;
    int Kper = K / kslices, kstart = blockIdx.z * Kper, nch = Kper >> 5;
    int wm = (wid & 1) * 64, wn = (wid >> 1) * 32;
    unsigned sm = smem_u32(smem);

    int r0 = tid >> 2, s0 = tid & 3;
    int f1 = tid + 256, r1 = f1 >> 2, s1 = f1 & 3;
    int szA0 = (m0 + r0 < M) ? 16 : 0, szA1 = (m0 + r1 < M) ? 16 : 0;
    const __nv_bfloat16* a0 = A + (size_t)(szA0 ? (m0 + r0) : 0) * K2 + s0 * 8;
    const __nv_bfloat16* a1 = A + (size_t)(szA1 ? (m0 + r1) : 0) * K2 + s1 * 8;
    const __nv_bfloat16* w0 = W + (size_t)(n0 + r0) * K2 + s0 * 8;
    const __nv_bfloat16* w1 = W + (size_t)(n0 + r1) * K2 + s1 * 8;
    unsigned o0 = (unsigned)(r0*SA + s0*8)*2, o1 = (unsigned)(r1*SA + s1*8)*2;

#define LOAD_STAGE(c, st) { \
    int kb = kstart + (c)*32; \
    unsigned so = sm + (unsigned)(st) * STGB; \
    cp16(so + o0,          a0 + kb,     szA0); cp16(so + o1,          a1 + kb,     szA1); \
    cp16(so + MATB + o0,   a0 + K + kb, szA0); cp16(so + MATB + o1,   a1 + K + kb, szA1); \
    cp16(so + 2*MATB + o0, w0 + kb,     16);   cp16(so + 2*MATB + o1, w1 + kb,     16); \
    cp16(so + 3*MATB + o0, w0 + K + kb, 16);   cp16(so + 3*MATB + o1, w1 + K + kb, 16); \
    asm volatile("cp.async.commit_group;"); }

    float acc[4][4][4];
#pragma unroll
    for (int a = 0; a < 4; a++)
#pragma unroll
        for (int b = 0; b < 4; b++)
#pragma unroll
            for (int c = 0; c < 4; c++) acc[a][b][c] = 0.f;

    LOAD_STAGE(0, 0);

    int g = lane >> 3, r = lane & 7;
    for (int c = 0; c < nch; c++) {
        if (c + 1 < nch) {
            LOAD_STAGE(c + 1, (c + 1) & 1);
            asm volatile("cp.async.wait_group 1;");
        } else {
            asm volatile("cp.async.wait_group 0;");
        }
        __syncthreads();
        unsigned st = sm + (unsigned)(c & 1) * STGB;
#pragma unroll
        for (int ks = 0; ks < 2; ks++) {
            unsigned afh[4][4], afl[4][4], bfh[4][2], bfl[4][2];
#pragma unroll
            for (int mt = 0; mt < 4; mt++) {
                unsigned roff = (unsigned)(((wm + mt*16 + (g & 1)*8 + r) * SA
                                   + ks*16 + (g >> 1)*8) * 2);
                asm volatile("ldmatrix.sync.aligned.m8n8.x4.shared.b16 {%0,%1,%2,%3}, [%4];"
                    : "=r"(afh[mt][0]), "=r"(afh[mt][1]), "=r"(afh[mt][2]), "=r"(afh[mt][3])
                    : "r"(st + roff));
                asm volatile("ldmatrix.sync.aligned.m8n8.x4.shared.b16 {%0,%1,%2,%3}, [%4];"
                    : "=r"(afl[mt][0]), "=r"(afl[mt][1]), "=r"(afl[mt][2]), "=r"(afl[mt][3])
                    : "r"(st + MATB + roff));
            }
#pragma unroll
            for (int np = 0; np < 2; np++) {
                unsigned roff = (unsigned)(((wn + np*16 + (g >> 1)*8 + r) * SA
                                   + ks*16 + (g & 1)*8) * 2);
                unsigned t0,t1,t2,t3;
                asm volatile("ldmatrix.sync.aligned.m8n8.x4.shared.b16 {%0,%1,%2,%3}, [%4];"
                    : "=r"(t0), "=r"(t1), "=r"(t2), "=r"(t3) : "r"(st + 2u*MATB + roff));
                bfh[2*np][0] = t0; bfh[2*np][1] = t1;
                bfh[2*np+1][0] = t2; bfh[2*np+1][1] = t3;
                asm volatile("ldmatrix.sync.aligned.m8n8.x4.shared.b16 {%0,%1,%2,%3}, [%4];"
                    : "=r"(t0), "=r"(t1), "=r"(t2), "=r"(t3) : "r"(st + 3u*MATB + roff));
                bfl[2*np][0] = t0; bfl[2*np][1] = t1;
                bfl[2*np+1][0] = t2; bfl[2*np+1][1] = t3;
            }
#define MMA16(AF, BF) \
_Pragma("unroll") \
            for (int mt = 0; mt < 4; mt++) \
_Pragma("unroll") \
                for (int nt = 0; nt < 4; nt++) { \
                    asm volatile( \
                        "mma.sync.aligned.m16n8k16.row.col.f32.bf16.bf16.f32 " \
                        "{%0,%1,%2,%3}, {%4,%5,%6,%7}, {%8,%9}, {%0,%1,%2,%3};" \
                        : "+f"(acc[mt][nt][0]), "+f"(acc[mt][nt][1]), \
                          "+f"(acc[mt][nt][2]), "+f"(acc[mt][nt][3]) \
                        : "r"(AF[mt][0]), "r"(AF[mt][1]), "r"(AF[mt][2]), "r"(AF[mt][3]), \
                          "r"(BF[nt][0]), "r"(BF[nt][1])); \
                }
            MMA16(afh, bfh)
            MMA16(afl, bfh)
            MMA16(afh, bfl)
#undef MMA16
        }
        __syncthreads();
    }

    size_t MN = (size_t)M * N;
    size_t base = (size_t)blockIdx.z * MN;
#pragma unroll
    for (int mt = 0; mt < 4; mt++) {
        int m = m0 + wm + mt*16 + (lane >> 2);
#pragma unroll
        for (int nt = 0; nt < 4; nt++) {
            int n = n0 + wn + nt*8 + (lane & 3)*2;
            if (m < M)
                *(float2*)(P + base + (size_t)m * N + n)
                    = make_float2(acc[mt][nt][0], acc[mt][nt][1]);
            if (m + 8 < M)
                *(float2*)(P + base + (size_t)(m+8) * N + n)
                    = make_float2(acc[mt][nt][2], acc[mt][nt][3]);
        }
    }
#undef LOAD_STAGE

    if (!fuse) return;

    // ---- deterministic last-block reduction + epilogue ----
    __threadfence();
    __shared__ int lastf;
    if (tid == 0) {
        int tile = blockIdx.x * gridDim.y + blockIdx.y;
        int old = atomicAdd(&cnt[tile], 1);
        int is_last = (old == kslices - 1);
        if (is_last) cnt[tile] = 0;          // self-reset for next launch/replay
        lastf = is_last;
    }
    __syncthreads();
    if (!lastf) return;
    __threadfence();

    for (int it = 0; it < 16; it++) {
        int chunk = tid + it * 256;          // 128 rows x 32 col-chunks
        int row = chunk >> 5, colc = chunk & 31;
        int m = m0 + row, n = n0 + colc * 4;
        if (m >= M) continue;
        float4 v = make_float4(0.f,0.f,0.f,0.f);
        for (int z = 0; z < kslices; z++) {
            float4 p = *(const float4*)(P + (size_t)z * MN + (size_t)m * N + n);
            v.x += p.x; v.y += p.y; v.z += p.z; v.w += p.w;
        }
        float4 b4 = *(const float4*)(bias + n);
        v.x += b4.x; v.y += b4.y; v.z += b4.z; v.w += b4.w;
        if (gelu) { v.x = gelu_f(v.x); v.y = gelu_f(v.y); v.z = gelu_f(v.z); v.w = gelu_f(v.w); }
        if (res) {
            float4 r4 = *(const float4*)(res + (size_t)m * N + n);
            v.x += r4.x; v.y += r4.y; v.z += r4.z; v.w += r4.w;
        }
        if (out) *(float4*)(out + (size_t)m * N + n) = v;
        if (out2) {
            size_t idx = (size_t)m * N + n;
            if (idx + 4 <= (size_t)out2_lim) *(float4*)(out2 + idx) = v;
        }
        if (tout) whl4(tout, (size_t)m * 2 * N, N, n, v);
    }
}

// ---------------- fused epilogue + layernorm (N=1024; one block per row) ----------------
__global__ void epilogue_ln_kernel(const float* __restrict__ P, const float* __restrict__ bias,
                                   const float* __restrict__ res,
                                   const float* __restrict__ g, const float* __restrict__ be,
                                   float* __restrict__ epi_out, float* __restrict__ ln_out,
                                   __nv_bfloat16* __restrict__ tout,
                                   int M, int kslices)
{
    int m = blockIdx.x, t = threadIdx.x;      // 256 threads, 4 cols each
    __shared__ float red[256];
    int col = t * 4;
    size_t MN = (size_t)M * HH;
    const float* Pm = P + (size_t)m * HH + col;
    float4 v = make_float4(0.f,0.f,0.f,0.f);
    for (int s = 0; s < kslices; s++) {
        float4 p = *(const float4*)(Pm + (size_t)s * MN);
        v.x += p.x; v.y += p.y; v.z += p.z; v.w += p.w;
    }
    float4 b4 = *(const float4*)(bias + col);
    v.x += b4.x; v.y += b4.y; v.z += b4.z; v.w += b4.w;
    if (res) {
        float4 r4 = *(const float4*)(res + (size_t)m * HH + col);
        v.x += r4.x; v.y += r4.y; v.z += r4.z; v.w += r4.w;
    }
    if (epi_out) *(float4*)(epi_out + (size_t)m * HH + col) = v;

    red[t] = v.x + v.y + v.z + v.w; __syncthreads();
    for (int o = 128; o > 0; o >>= 1) { if (t < o) red[t] += red[t+o]; __syncthreads(); }
    float mean = red[0] * (1.f / HH);
    __syncthreads();
    float dx = v.x - mean, dy = v.y - mean, dz = v.z - mean, dw = v.w - mean;
    red[t] = dx*dx + dy*dy + dz*dz + dw*dw; __syncthreads();
    for (int o = 128; o > 0; o >>= 1) { if (t < o) red[t] += red[t+o]; __syncthreads(); }
    float inv = rsqrtf(red[0] * (1.f / HH) + 1e-5f);

    float4 g4 = *(const float4*)(g + col);
    float4 e4 = *(const float4*)(be + col);
    float4 o4;
    o4.x = dx * inv * g4.x + e4.x;
    o4.y = dy * inv * g4.y + e4.y;
    o4.z = dz * inv * g4.z + e4.z;
    o4.w = dw * inv * g4.w + e4.w;
    if (ln_out) *(float4*)(ln_out + (size_t)m * HH + col) = o4;
    whl4(tout, (size_t)m * 2048, 1024, col, o4);
}

// ---------------- fused gelu-epilogue + salience logits ----------------
__global__ void epilogue_logits_kernel(const float* __restrict__ P, const float* __restrict__ bias,
                                       const float* __restrict__ w2, const float* __restrict__ b2,
                                       int M, int kslices)
{
    int m = blockIdx.x, t = threadIdx.x;  // 256
    __shared__ float red[256];
    int col = t * 4;
    size_t MN = (size_t)M * HH;
    const float* Pm = P + (size_t)m * HH + col;
    float4 v = make_float4(0.f,0.f,0.f,0.f);
    for (int s = 0; s < kslices; s++) {
        float4 p = *(const float4*)(Pm + (size_t)s * MN);
        v.x += p.x; v.y += p.y; v.z += p.z; v.w += p.w;
    }
    float4 b4 = *(const float4*)(bias + col);
    v.x = gelu_f(v.x + b4.x); v.y = gelu_f(v.y + b4.y);
    v.z = gelu_f(v.z + b4.z); v.w = gelu_f(v.w + b4.w);
    float4 w = *(const float4*)(w2 + col);
    red[t] = v.x*w.x + v.y*w.y + v.z*w.z + v.w*w.w; __syncthreads();
    for (int o = 128; o > 0; o >>= 1) { if (t < o) red[t] += red[t+o]; __syncthreads(); }
    if (t == 0) g_logits[m] = red[0] + b2[0];
}

// ---------------- small attention: one (b, head) per block; bf16 hi|lo output ----------------
__global__ void attn_kernel(const float* __restrict__ qb, const float* __restrict__ kb,
                            const float* __restrict__ vb, __nv_bfloat16* __restrict__ tout,
                            int NQ, int NK,
                            int qRowStr, long long qBatStr,
                            int kRowStr, long long kBatStr,
                            int vRowStr, long long vBatStr)
{
    int b = blockIdx.x, hd = blockIdx.y;
    const float* q = qb + b * qBatStr + hd * DHD;
    const float* k = kb + b * kBatStr + hd * DHD;
    const float* v = vb + b * vBatStr + hd * DHD;
    __shared__ float qs[16][DHD+1], ks[16][DHD+1], vs[16][DHD+1];
    __shared__ float pr[16][17];
    int t = threadIdx.x;  // 128
    for (int i = 0; i < NQ; i++) qs[i][t] = q[(size_t)i * qRowStr + t];
    for (int i = 0; i < NK; i++) { ks[i][t] = k[(size_t)i * kRowStr + t]; vs[i][t] = v[(size_t)i * vRowStr + t]; }
    __syncthreads();
    const float scale = 0.08838834764831843f;   // 1/sqrt(128)
    for (int p = t; p < NQ * NK; p += 128) {
        int qi = p / NK, ki = p - qi * NK;
        float acc = 0.f;
#pragma unroll 4
        for (int d = 0; d < DHD; d++) acc = fmaf(qs[qi][d], ks[ki][d], acc);
        pr[qi][ki] = acc * scale;
    }
    __syncthreads();
    if (t < NQ) {
        float mx = -1e30f;
        for (int kk = 0; kk < NK; kk++) mx = fmaxf(mx, pr[t][kk]);
        float sm = 0.f;
        for (int kk = 0; kk < NK; kk++) { float e = expf(pr[t][kk] - mx); pr[t][kk] = e; sm += e; }
        float inv = 1.f / sm;
        for (int kk = 0; kk < NK; kk++) pr[t][kk] *= inv;
    }
    __syncthreads();
    for (int j = t; j < NQ * DHD; j += 128) {
        int qi = j >> 7, d = j & 127;
        float acc = 0.f;
        for (int kk = 0; kk < NK; kk++) acc = fmaf(pr[qi][kk], vs[kk][d], acc);
        whl(tout, (size_t)(b * NQ + qi) * 2048, 1024, hd * DHD + d, acc);
    }
}

// ---------------- salience softmax + entropy + weighted segments (bf16 out) ----------------
__global__ void salience_kernel() {
    int b = blockIdx.x, t = threadIdx.x;  // 256
    __shared__ float sal_s[NS];
    if (b == 0 && t == 0) g_red_cnt = 0;    // reset for fused red+finalize
    if (t == 0) {
        float mx = -1e30f;
        for (int s = 0; s < NS; s++) mx = fmaxf(mx, g_logits[b*NS + s]);
        float sm = 0.f;
        for (int s = 0; s < NS; s++) { float e = expf(g_logits[b*NS + s] - mx); sal_s[s] = e; sm += e; }
        float inv = 1.f / sm, ent = 0.f;
        for (int s = 0; s < NS; s++) {
            sal_s[s] *= inv;
            g_sal[b*NS + s] = sal_s[s];
            ent -= sal_s[s] * logf(sal_s[s] + 1e-8f);
        }
        g_entpart[b] = ent;
    }
    __syncthreads();
    for (int i = t; i < NS * HH; i += 256) {
        int s = i >> 10, k = i & 1023;
        float v = g_seg1[(size_t)b * NS * HH + i] * sal_s[s];
        whl(g_bf_wseg, (size_t)(b * NS + s) * 2048, 1024, k, v);
    }
}

// ---------------- redundancy + fused finalize (last block) ----------------
__global__ void red_kernel(float* __restrict__ out, int out_size) {
    int b = blockIdx.x, t = threadIdx.x;  // 128
    __shared__ float ps[NP][HH+1];
    __shared__ float nrm[NP];
    __shared__ float parr[16];
    __shared__ int lastflag;
    for (int i = t; i < NP * HH; i += 128) ps[i >> 10][i & 1023] = g_plan[(size_t)b * NP * HH + i];
    __syncthreads();
    if (t < NP) {
        float s = 0.f;
        for (int d = 0; d < HH; d++) s = fmaf(ps[t][d], ps[t][d], s);
        nrm[t] = fmaxf(sqrtf(s), 1e-12f);
    }
    __syncthreads();
    if (t < 15) {
        int i = 0, j = 0, c = t;
        for (i = 0; i < NP; i++) { int row = NP - 1 - i; if (c < row) { j = i + 1 + c; break; } c -= row; }
        float s = 0.f;
        for (int d = 0; d < HH; d++) s = fmaf(ps[i][d], ps[j][d], s);
        float sim = s / (nrm[i] * nrm[j]);
        parr[t] = 2.f * sim * sim;
    }
    __syncthreads();
    if (t == 0) {
        float s = 0.f;
        for (int p = 0; p < 15; p++) s += parr[p];
        g_redpart[b] = s;
        __threadfence();
        int old = atomicAdd(&g_red_cnt, 1);
        lastflag = (old == NB - 1);
    }
    __syncthreads();
    if (lastflag) {
        for (int i = t; i < NB*NS; i += 128)
            if (PLAN_ELEMS + i < out_size) out[PLAN_ELEMS + i] = g_sal[i];
        if (t == 0) {
            if (PLAN_ELEMS + 256 < out_size) {
                float e = 0.f;
                for (int bb = 0; bb < NB; bb++) e += g_entpart[bb];
                out[PLAN_ELEMS + 256] = e / (float)NB;
            }
            if (PLAN_ELEMS + 257 < out_size) {
                float r = 0.f;
                for (int bb = 0; bb < NB; bb++) r += g_redpart[bb];
                out[PLAN_ELEMS + 257] = r / (float)(NB * NP * (NP - 1));
            }
        }
    }
}

// ---------------- host helpers ----------------
// ks: (K/ks) % 32 == 0; ks*M*N <= partial region size
static void gemm_plain(const __nv_bfloat16* A, const __nv_bfloat16* W, int M, int N, int K, int ks,
                       float* part, cudaStream_t st = 0)
{
    dim3 grid((M + 127) / 128, N / 128, ks);
    gemm_bf16_kernel<<<grid, 256, 2*STGB, st>>>(A, W, part, M, N, K, ks,
        0, nullptr, nullptr, nullptr, nullptr, 0, nullptr, 0, nullptr);
}
static void gemm_fused(const __nv_bfloat16* A, const __nv_bfloat16* W, int M, int N, int K, int ks,
                       float* part, const float* bias, const float* res,
                       float* out, float* out2, int out2_lim,
                       __nv_bfloat16* tout, int gelu, int* cnt, cudaStream_t st = 0)
{
    dim3 grid((M + 127) / 128, N / 128, ks);
    gemm_bf16_kernel<<<grid, 256, 2*STGB, st>>>(A, W, part, M, N, K, ks,
        1, bias, res, out, out2, out2_lim, tout, gelu, cnt);
}

extern "C" void kernel_launch(void* const* d_in, const int* in_sizes, int n_in,
                              void* d_out, int out_size)
{
    const float* ts       = (const float*)d_in[0];
    const int*   mask     = (const int*)  d_in[1];
    const float* sa_in_w  = (const float*)d_in[2];
    const float* sa_in_b  = (const float*)d_in[3];
    const float* sa_out_w = (const float*)d_in[4];
    const float* sa_out_b = (const float*)d_in[5];
    const float* ln_g     = (const float*)d_in[6];
    const float* ln_b     = (const float*)d_in[7];
    const float* sal_w1   = (const float*)d_in[8];
    const float* sal_b1   = (const float*)d_in[9];
    const float* sal_w2   = (const float*)d_in[10];
    const float* sal_b2   = (const float*)d_in[11];
    const float* plan_q   = (const float*)d_in[12];
    const float* qa_in_w  = (const float*)d_in[13];
    const float* qa_in_b  = (const float*)d_in[14];
    const float* qa_out_w = (const float*)d_in[15];
    const float* qa_out_b = (const float*)d_in[16];
    const float* r_in_w   = (const float*)d_in[17];
    const float* r_in_b   = (const float*)d_in[18];
    const float* r_out_w  = (const float*)d_in[19];
    const float* r_out_b  = (const float*)d_in[20];
    const float* r_ln1_g  = (const float*)d_in[21];
    const float* r_ln1_b  = (const float*)d_in[22];
    const float* r_ln2_g  = (const float*)d_in[23];
    const float* r_ln2_b  = (const float*)d_in[24];
    const float* r_w1     = (const float*)d_in[25];
    const float* r_b1     = (const float*)d_in[26];
    const float* r_w2     = (const float*)d_in[27];
    const float* r_b2     = (const float*)d_in[28];
    float* out = (float*)d_out;

    static int init_done = 0;
    static cudaStream_t s2;
    static cudaEvent_t ev_fork, ev_join, ev_q;
    if (!init_done) {
        cudaFuncSetAttribute(gemm_bf16_kernel,
                             cudaFuncAttributeMaxDynamicSharedMemorySize, 2*STGB);
        cudaStreamCreateWithFlags(&s2, cudaStreamNonBlocking);
        cudaEventCreateWithFlags(&ev_fork, cudaEventDisableTiming);
        cudaEventCreateWithFlags(&ev_join, cudaEventDisableTiming);
        cudaEventCreateWithFlags(&ev_q, cudaEventDisableTiming);
        init_done = 1;
    }

    float *p_part, *p_qkv, *p_seg1, *p_qh, *p_kv, *p_plan, *p_qkvr, *p_seg0;
    cudaGetSymbolAddress((void**)&p_part, g_part);
    cudaGetSymbolAddress((void**)&p_seg0, g_seg0);
    cudaGetSymbolAddress((void**)&p_qkv,  g_qkv);
    cudaGetSymbolAddress((void**)&p_seg1, g_seg1);
    cudaGetSymbolAddress((void**)&p_qh,   g_qh);
    cudaGetSymbolAddress((void**)&p_kv,   g_kv);
    cudaGetSymbolAddress((void**)&p_plan, g_plan);
    cudaGetSymbolAddress((void**)&p_qkvr, g_qkvr);
    int* p_cnt;
    cudaGetSymbolAddress((void**)&p_cnt, g_tilecnt);

    __nv_bfloat16 *t_seg0, *t_o, *t_seg1, *t_wseg, *t_pq, *t_o2, *t_y, *t_o3, *t_ffn, *wbf;
    cudaGetSymbolAddress((void**)&t_seg0, g_bf_seg0);
    cudaGetSymbolAddress((void**)&t_o,    g_bf_o);
    cudaGetSymbolAddress((void**)&t_seg1, g_bf_seg1);
    cudaGetSymbolAddress((void**)&t_wseg, g_bf_wseg);
    cudaGetSymbolAddress((void**)&t_pq,   g_bf_pq);
    cudaGetSymbolAddress((void**)&t_o2,   g_bf_o2);
    cudaGetSymbolAddress((void**)&t_y,    g_bf_y);
    cudaGetSymbolAddress((void**)&t_o3,   g_bf_o3);
    cudaGetSymbolAddress((void**)&t_ffn,  g_bf_ffn);
    cudaGetSymbolAddress((void**)&wbf,    g_wbf);

    // 0) weight conversion + qh projection forked onto side stream
    CvtTab tab;
    tab.src[0]=sa_in_w;  tab.dst[0]=wbf+WOFF_SAIN;  tab.n[0]=3145728; tab.logK[0]=10;
    tab.src[1]=sa_out_w; tab.dst[1]=wbf+WOFF_SAOUT; tab.n[1]=1048576; tab.logK[1]=10;
    tab.src[2]=sal_w1;   tab.dst[2]=wbf+WOFF_SAL1;  tab.n[2]=1048576; tab.logK[2]=10;
    tab.src[3]=qa_in_w;  tab.dst[3]=wbf+WOFF_QAIN;  tab.n[3]=3145728; tab.logK[3]=10;
    tab.src[4]=qa_out_w; tab.dst[4]=wbf+WOFF_QAOUT; tab.n[4]=1048576; tab.logK[4]=10;
    tab.src[5]=r_in_w;   tab.dst[5]=wbf+WOFF_RIN;   tab.n[5]=6291456; tab.logK[5]=10;
    tab.src[6]=r_out_w;  tab.dst[6]=wbf+WOFF_ROUT;  tab.n[6]=2097152; tab.logK[6]=10;
    tab.src[7]=r_w1;     tab.dst[7]=wbf+WOFF_RW1;   tab.n[7]=8388608; tab.logK[7]=10;
    tab.src[8]=r_w2;     tab.dst[8]=wbf+WOFF_RW2;   tab.n[8]=8388608; tab.logK[8]=12;
    tab.src[9]=plan_q;   tab.dst[9]=t_pq;           tab.n[9]=6144;    tab.logK[9]=10;

    cudaEventRecord(ev_fork, 0);
    cudaStreamWaitEvent(s2, ev_fork, 0);
    convert_kernel<<<dim3(2048, 10), 256, 0, s2>>>(tab);
    cudaEventRecord(ev_join, s2);
    // qh projection: depends only on converted weights; own partial + counter region
    gemm_fused(t_pq, wbf+WOFF_QAIN, NP, HH, HH, 32, p_part + 7*1024*1024,
               qa_in_b, nullptr, p_qh, nullptr, 0, nullptr, 0, p_cnt + 256, s2);
    cudaEventRecord(ev_q, s2);

    // 1) lengths + bounds, fused segment pooling (main stream, overlaps convert)
    lengths_kernel<<<16, 256>>>(mask);
    segpool_kernel<<<NB*NS, 256>>>(ts);

    // join: GEMMs below need converted weights
    cudaStreamWaitEvent(0, ev_join, 0);

    // 2) segment self-attention
    gemm_fused(t_seg0, wbf+WOFF_SAIN, 256, 3*HH, HH, 8, p_part,
               sa_in_b, nullptr, p_qkv, nullptr, 0, nullptr, 0, p_cnt);
    attn_kernel<<<dim3(NB, NHEAD), 128>>>(p_qkv, p_qkv + HH, p_qkv + 2*HH, t_o,
                                          16, 16,
                                          3*HH, (long long)NS*3*HH,
                                          3*HH, (long long)NS*3*HH,
                                          3*HH, (long long)NS*3*HH);
    gemm_plain(t_o, wbf+WOFF_SAOUT, 256, HH, HH, 16, p_part);
    epilogue_ln_kernel<<<256, 256>>>(p_part, sa_out_b, p_seg0, ln_g, ln_b,
                                     nullptr, p_seg1, t_seg1, 256, 16);

    // 3) salience (gelu-epilogue + logits fused)
    gemm_plain(t_seg1, wbf+WOFF_SAL1, 256, HH, HH, 16, p_part);
    epilogue_logits_kernel<<<256, 256>>>(p_part, sal_b1, sal_w2, sal_b2, 256, 16);
    salience_kernel<<<16, 256>>>();

    // 4) plan cross-attention (qh computed on side stream)
    gemm_fused(t_wseg, wbf+WOFF_QAIN + (size_t)HH*2*HH, 256, 2*HH, HH, 8, p_part,
               qa_in_b + HH, nullptr, p_kv, nullptr, 0, nullptr, 0, p_cnt);
    cudaStreamWaitEvent(0, ev_q, 0);
    attn_kernel<<<dim3(NB, NHEAD), 128>>>(p_qh, p_kv, p_kv + HH, t_o2,
                                          NP, 16,
                                          HH,   0LL,
                                          2*HH, (long long)NS*2*HH,
                                          2*HH, (long long)NS*2*HH);
    gemm_plain(t_o2, wbf+WOFF_QAOUT, NB*NP, HH, HH, 16, p_part);
    epilogue_ln_kernel<<<NB*NP, 256>>>(p_part, qa_out_b, nullptr, r_ln1_g, r_ln1_b,
                                       p_plan, nullptr, t_y, NB*NP, 16);

    // 5) refinement transformer layers (norm_first)
    for (int l = 0; l < 2; l++) {
        gemm_fused(t_y, wbf+WOFF_RIN + (size_t)l*6291456, NB*NP, 3*HH, HH, 8, p_part,
                   r_in_b + l*3*HH, nullptr, p_qkvr, nullptr, 0, nullptr, 0, p_cnt);
        attn_kernel<<<dim3(NB, NHEAD), 128>>>(p_qkvr, p_qkvr + HH, p_qkvr + 2*HH, t_o3,
                                              NP, NP,
                                              3*HH, (long long)NP*3*HH,
                                              3*HH, (long long)NP*3*HH,
                                              3*HH, (long long)NP*3*HH);
        gemm_plain(t_o3, wbf+WOFF_ROUT + (size_t)l*2097152, NB*NP, HH, HH, 16, p_part);
        epilogue_ln_kernel<<<NB*NP, 256>>>(p_part, r_out_b + l*HH, p_plan,
                                           r_ln2_g + l*HH, r_ln2_b + l*HH,
                                           p_plan, nullptr, t_y, NB*NP, 16);
        gemm_fused(t_y, wbf+WOFF_RW1 + (size_t)l*8388608, NB*NP, 4*HH, HH, 8, p_part,
                   r_b1 + l*4*HH, nullptr, nullptr, nullptr, 0, t_ffn, 1, p_cnt);
        if (l == 0) {
            gemm_plain(t_ffn, wbf+WOFF_RW2, NB*NP, HH, 4*HH, 32, p_part);
            epilogue_ln_kernel<<<NB*NP, 256>>>(p_part, r_b2, p_plan,
                                               r_ln1_g + HH, r_ln1_b + HH,
                                               p_plan, nullptr, t_y, NB*NP, 32);
        } else {
            int lim = out_size < PLAN_ELEMS ? out_size : PLAN_ELEMS;
            gemm_fused(t_ffn, wbf+WOFF_RW2 + 8388608LL, NB*NP, HH, 4*HH, 32, p_part,
                       r_b2 + HH, p_plan, p_plan, out, lim, nullptr, 0, p_cnt);
        }
    }

    // 6) redundancy + finalize (fused)
    red_kernel<<<16, 128>>>(out, out_size);
}

// round 16
// speedup vs baseline: 1.1728x; 1.1728x over previous
#include <cuda_runtime.h>
#include <cuda_bf16.h>
#include <math.h>

// ---------------- problem constants ----------------
#define NB 16      // batch
#define NT 4096    // tokens
#define HH 1024    // hidden
#define NS 16      // segments
#define NP 6       // plan slots
#define NHEAD 8
#define DHD 128    // head dim
#define PLAN_ELEMS (NB*NP*HH)   // 98304

// ---------------- device scratch (static, no allocs) ----------------
__device__ int   g_bounds[NB*(NS+1)];
__device__ float g_seg0[NB*NS*HH];
__device__ float g_qkv[NB*NS*3*HH];
__device__ float g_seg1[NB*NS*HH];
__device__ float g_logits[NB*NS];
__device__ float g_sal[NB*NS];
__device__ float g_qh[NP*HH];
__device__ float g_kv[NB*NS*2*HH];
__device__ float g_plan[NB*NP*HH];
__device__ float g_qkvr[NB*NP*3*HH];
__device__ float g_part[8*1024*1024];          // split-K partials (32MB); qh region at +7M
__device__ float g_entpart[NB];
__device__ float g_redpart[NB];
__device__ int   g_red_cnt;

// bf16 [hi(K)|lo(K)] operand buffers
__device__ __nv_bfloat16 g_bf_seg0[256*2048];
__device__ __nv_bfloat16 g_bf_o   [256*2048];
__device__ __nv_bfloat16 g_bf_seg1[256*2048];
__device__ __nv_bfloat16 g_bf_wseg[256*2048];
__device__ __nv_bfloat16 g_bf_pq  [NP*2048];
__device__ __nv_bfloat16 g_bf_o2  [96*2048];
__device__ __nv_bfloat16 g_bf_y   [96*2048];
__device__ __nv_bfloat16 g_bf_o3  [96*2048];
__device__ __nv_bfloat16 g_bf_ffn [96*8192];
__device__ __nv_bfloat16 g_wbf[69206016];      // all weights hi|lo (138MB)

// weight offsets into g_wbf (bf16 elems)
#define WOFF_SAIN   0LL
#define WOFF_SAOUT  6291456LL
#define WOFF_SAL1   8388608LL
#define WOFF_QAIN   10485760LL
#define WOFF_QAOUT  16777216LL
#define WOFF_RIN    18874368LL
#define WOFF_ROUT   31457280LL
#define WOFF_RW1    35651584LL
#define WOFF_RW2    52428800LL

// ---------------- helpers ----------------
__device__ __forceinline__ unsigned smem_u32(const void* p) {
    unsigned a;
    asm("{ .reg .u64 t; cvta.to.shared.u64 t, %1; cvt.u32.u64 %0, t; }" : "=r"(a) : "l"(p));
    return a;
}
__device__ __forceinline__ unsigned pack_pair(float f0, float f1, bool lo) {
    if (lo) {
        f0 = f0 - __bfloat162float(__float2bfloat16(f0));
        f1 = f1 - __bfloat162float(__float2bfloat16(f1));
    }
    __nv_bfloat162 p = __floats2bfloat162_rn(f0, f1);
    return *reinterpret_cast<unsigned*>(&p);
}
__device__ __forceinline__ void cp16(unsigned dst, const void* src, int sz) {
    asm volatile("cp.async.ca.shared.global [%0], [%1], 16, %2;"
                 :: "r"(dst), "l"(src), "r"(sz));
}
__device__ __forceinline__ void whl(__nv_bfloat16* t, size_t rowbase, int K, int k, float v) {
    __nv_bfloat16 h = __float2bfloat16(v);
    __nv_bfloat16 l = __float2bfloat16(v - __bfloat162float(h));
    t[rowbase + k] = h;
    t[rowbase + K + k] = l;
}
__device__ __forceinline__ void whl4(__nv_bfloat16* t, size_t rowbase, int N, int col, float4 v) {
    unsigned h0 = pack_pair(v.x, v.y, false), h1 = pack_pair(v.z, v.w, false);
    unsigned l0 = pack_pair(v.x, v.y, true),  l1 = pack_pair(v.z, v.w, true);
    __nv_bfloat16* tr = t + rowbase + col;
    *(uint2*)tr       = make_uint2(h0, h1);
    *(uint2*)(tr + N) = make_uint2(l0, l1);
}
__device__ __forceinline__ float gelu_f(float v) {
    return 0.5f * v * (1.f + erff(v * 0.70710678118654752f));
}

// ---------------- weight conversion (all tensors, one launch) ----------------
struct CvtTab {
    const float* src[10];
    __nv_bfloat16* dst[10];
    int n[10];
    int logK[10];
};
__global__ void convert_kernel(CvtTab tab) {
    int tsel = blockIdx.y;
    const float* s = tab.src[tsel];
    __nv_bfloat16* d = tab.dst[tsel];
    long long n = tab.n[tsel];
    int logK = tab.logK[tsel];
    int K = 1 << logK;
    long long stride = (long long)gridDim.x * blockDim.x * 4;
    for (long long idx = ((long long)blockIdx.x * blockDim.x + threadIdx.x) * 4;
         idx < n; idx += stride) {
        float4 v = *(const float4*)(s + idx);
        int k = (int)(idx & (K - 1));
        long long row = idx >> logK;
        __nv_bfloat16* dr = d + row * (2LL * K) + k;
        unsigned h0 = pack_pair(v.x, v.y, false), h1 = pack_pair(v.z, v.w, false);
        unsigned l0 = pack_pair(v.x, v.y, true),  l1 = pack_pair(v.z, v.w, true);
        *(uint2*)dr       = make_uint2(h0, h1);
        *(uint2*)(dr + K) = make_uint2(l0, l1);
    }
}

// ---------------- lengths + segment bounds ----------------
__global__ void lengths_kernel(const int* __restrict__ mask) {
    int b = blockIdx.x;
    __shared__ int red[256];
    int t = threadIdx.x;
    int s = 0;
    for (int i = t; i < NT; i += 256) s += mask[b*NT + i];
    red[t] = s; __syncthreads();
    for (int o = 128; o > 0; o >>= 1) { if (t < o) red[t] += red[t+o]; __syncthreads(); }
    if (t == 0) {
        int L = red[0];
        for (int k = 0; k <= NS; k++) g_bounds[b*(NS+1) + k] = (k * L) / NS;
    }
}

// ---------------- fused segment pooling (single kernel, 8-row unrolled) ----------------
__global__ void segpool_kernel(const float* __restrict__ ts) {
    int seg = blockIdx.x;                 // 0..255
    int b = seg >> 4, s = seg & 15;
    int lo = g_bounds[b*(NS+1) + s], hi = g_bounds[b*(NS+1) + s + 1];
    int cnt = hi - lo;
    int t = threadIdx.x;                  // 256 threads, 4 cols each
    const float* base = ts + (size_t)b * NT * HH + t * 4;
    float4 a[8];
#pragma unroll
    for (int i = 0; i < 8; i++) a[i] = make_float4(0.f,0.f,0.f,0.f);
    int r = lo;
    for (; r + 8 <= hi; r += 8) {
#pragma unroll
        for (int i = 0; i < 8; i++) {
            float4 v = *(const float4*)(base + (size_t)(r+i) * HH);
            a[i].x += v.x; a[i].y += v.y; a[i].z += v.z; a[i].w += v.w;
        }
    }
    for (; r < hi; r++) {
        float4 v = *(const float4*)(base + (size_t)r * HH);
        a[0].x += v.x; a[0].y += v.y; a[0].z += v.z; a[0].w += v.w;
    }
#pragma unroll
    for (int i = 1; i < 8; i++) {
        a[0].x += a[i].x; a[0].y += a[i].y; a[0].z += a[i].z; a[0].w += a[i].w;
    }
    float inv = 1.f / fmaxf((float)cnt, 1.f);
    float4 v = make_float4(a[0].x * inv, a[0].y * inv, a[0].z * inv, a[0].w * inv);
    *(float4*)&g_seg0[(size_t)seg * HH + t*4] = v;
    whl4(g_bf_seg0, (size_t)seg * 2048, 1024, t*4, v);
}

// ---------------- bf16 split-K GEMM (compensated, fragment-reuse, cp.async 2-stage) ----------------
// D = A_hi*W_hi + A_lo*W_hi + A_hi*W_lo.  A,W stored [rows, 2K] = [hi(K)|lo(K)].
// 128x128 tile, BK=32, 256 thr, 8 warps 64x32. Per k16 step: load af_hi/af_lo/bf_hi/bf_lo
// fragments ONCE, run the 3 phase mma groups from registers.
#define SA 40   // padded smem row stride (bf16) => 80B
#define MATB (128*SA*2)        // 10240 bytes per tile
#define STGB (4*MATB)          // 40960 bytes per stage

__global__ void __launch_bounds__(256) gemm_bf16_kernel(
    const __nv_bfloat16* __restrict__ A, const __nv_bfloat16* __restrict__ W,
    float* __restrict__ P, int M, int N, int K, int kslices)
{
    extern __shared__ __align__(16) unsigned char smem[];
    int tid = threadIdx.x, wid = tid >> 5, lane = tid & 31;
    int m0 = blockIdx.x * 128, n0 = blockIdx.y * 128;
    int K2 = 2 * K;
    int Kper = K / kslices, kstart = blockIdx.z * Kper, nch = Kper >> 5;
    int wm = (wid & 1) * 64, wn = (wid >> 1) * 32;
    unsigned sm = smem_u32(smem);

    int r0 = tid >> 2, s0 = tid & 3;
    int f1 = tid + 256, r1 = f1 >> 2, s1 = f1 & 3;
    int szA0 = (m0 + r0 < M) ? 16 : 0, szA1 = (m0 + r1 < M) ? 16 : 0;
    const __nv_bfloat16* a0 = A + (size_t)(szA0 ? (m0 + r0) : 0) * K2 + s0 * 8;
    const __nv_bfloat16* a1 = A + (size_t)(szA1 ? (m0 + r1) : 0) * K2 + s1 * 8;
    const __nv_bfloat16* w0 = W + (size_t)(n0 + r0) * K2 + s0 * 8;
    const __nv_bfloat16* w1 = W + (size_t)(n0 + r1) * K2 + s1 * 8;
    unsigned o0 = (unsigned)(r0*SA + s0*8)*2, o1 = (unsigned)(r1*SA + s1*8)*2;

#define LOAD_STAGE(c, st) { \
    int kb = kstart + (c)*32; \
    unsigned so = sm + (unsigned)(st) * STGB; \
    cp16(so + o0,          a0 + kb,     szA0); cp16(so + o1,          a1 + kb,     szA1); \
    cp16(so + MATB + o0,   a0 + K + kb, szA0); cp16(so + MATB + o1,   a1 + K + kb, szA1); \
    cp16(so + 2*MATB + o0, w0 + kb,     16);   cp16(so + 2*MATB + o1, w1 + kb,     16); \
    cp16(so + 3*MATB + o0, w0 + K + kb, 16);   cp16(so + 3*MATB + o1, w1 + K + kb, 16); \
    asm volatile("cp.async.commit_group;"); }

    float acc[4][4][4];
#pragma unroll
    for (int a = 0; a < 4; a++)
#pragma unroll
        for (int b = 0; b < 4; b++)
#pragma unroll
            for (int c = 0; c < 4; c++) acc[a][b][c] = 0.f;

    LOAD_STAGE(0, 0);

    int g = lane >> 3, r = lane & 7;
    for (int c = 0; c < nch; c++) {
        if (c + 1 < nch) {
            LOAD_STAGE(c + 1, (c + 1) & 1);
            asm volatile("cp.async.wait_group 1;");
        } else {
            asm volatile("cp.async.wait_group 0;");
        }
        __syncthreads();
        unsigned st = sm + (unsigned)(c & 1) * STGB;
#pragma unroll
        for (int ks = 0; ks < 2; ks++) {
            unsigned afh[4][4], afl[4][4], bfh[4][2], bfl[4][2];
#pragma unroll
            for (int mt = 0; mt < 4; mt++) {
                unsigned roff = (unsigned)(((wm + mt*16 + (g & 1)*8 + r) * SA
                                   + ks*16 + (g >> 1)*8) * 2);
                asm volatile("ldmatrix.sync.aligned.m8n8.x4.shared.b16 {%0,%1,%2,%3}, [%4];"
                    : "=r"(afh[mt][0]), "=r"(afh[mt][1]), "=r"(afh[mt][2]), "=r"(afh[mt][3])
                    : "r"(st + roff));
                asm volatile("ldmatrix.sync.aligned.m8n8.x4.shared.b16 {%0,%1,%2,%3}, [%4];"
                    : "=r"(afl[mt][0]), "=r"(afl[mt][1]), "=r"(afl[mt][2]), "=r"(afl[mt][3])
                    : "r"(st + MATB + roff));
            }
#pragma unroll
            for (int np = 0; np < 2; np++) {
                unsigned roff = (unsigned)(((wn + np*16 + (g >> 1)*8 + r) * SA
                                   + ks*16 + (g & 1)*8) * 2);
                unsigned t0,t1,t2,t3;
                asm volatile("ldmatrix.sync.aligned.m8n8.x4.shared.b16 {%0,%1,%2,%3}, [%4];"
                    : "=r"(t0), "=r"(t1), "=r"(t2), "=r"(t3) : "r"(st + 2u*MATB + roff));
                bfh[2*np][0] = t0; bfh[2*np][1] = t1;
                bfh[2*np+1][0] = t2; bfh[2*np+1][1] = t3;
                asm volatile("ldmatrix.sync.aligned.m8n8.x4.shared.b16 {%0,%1,%2,%3}, [%4];"
                    : "=r"(t0), "=r"(t1), "=r"(t2), "=r"(t3) : "r"(st + 3u*MATB + roff));
                bfl[2*np][0] = t0; bfl[2*np][1] = t1;
                bfl[2*np+1][0] = t2; bfl[2*np+1][1] = t3;
            }
#define MMA16(AF, BF) \
_Pragma("unroll") \
            for (int mt = 0; mt < 4; mt++) \
_Pragma("unroll") \
                for (int nt = 0; nt < 4; nt++) { \
                    asm volatile( \
                        "mma.sync.aligned.m16n8k16.row.col.f32.bf16.bf16.f32 " \
                        "{%0,%1,%2,%3}, {%4,%5,%6,%7}, {%8,%9}, {%0,%1,%2,%3};" \
                        : "+f"(acc[mt][nt][0]), "+f"(acc[mt][nt][1]), \
                          "+f"(acc[mt][nt][2]), "+f"(acc[mt][nt][3]) \
                        : "r"(AF[mt][0]), "r"(AF[mt][1]), "r"(AF[mt][2]), "r"(AF[mt][3]), \
                          "r"(BF[nt][0]), "r"(BF[nt][1])); \
                }
            MMA16(afh, bfh)
            MMA16(afl, bfh)
            MMA16(afh, bfl)
#undef MMA16
        }
        __syncthreads();
    }

    size_t base = (size_t)blockIdx.z * M * N;
#pragma unroll
    for (int mt = 0; mt < 4; mt++) {
        int m = m0 + wm + mt*16 + (lane >> 2);
#pragma unroll
        for (int nt = 0; nt < 4; nt++) {
            int n = n0 + wn + nt*8 + (lane & 3)*2;
            if (m < M)
                *(float2*)(P + base + (size_t)m * N + n)
                    = make_float2(acc[mt][nt][0], acc[mt][nt][1]);
            if (m + 8 < M)
                *(float2*)(P + base + (size_t)(m+8) * N + n)
                    = make_float2(acc[mt][nt][2], acc[mt][nt][3]);
        }
    }
#undef LOAD_STAGE
}

// ---------------- plain epilogue (vectorized) ----------------
__global__ void epilogue_kernel(const float* __restrict__ P, const float* __restrict__ bias,
                                const float* __restrict__ res, float* __restrict__ out,
                                float* __restrict__ out2, int out2_lim,
                                __nv_bfloat16* __restrict__ tout,
                                int M, int N, int kslices, int gelu)
{
    int idx = (blockIdx.x * 256 + threadIdx.x) * 4;
    if (idx >= M * N) return;
    int n = idx % N, m = idx / N;
    size_t MN = (size_t)M * N;
    float4 v = make_float4(0.f,0.f,0.f,0.f);
    for (int s = 0; s < kslices; s++) {
        float4 p = *(const float4*)(P + (size_t)s * MN + idx);
        v.x += p.x; v.y += p.y; v.z += p.z; v.w += p.w;
    }
    float4 b4 = *(const float4*)(bias + n);
    v.x += b4.x; v.y += b4.y; v.z += b4.z; v.w += b4.w;
    if (gelu) { v.x = gelu_f(v.x); v.y = gelu_f(v.y); v.z = gelu_f(v.z); v.w = gelu_f(v.w); }
    if (res) {
        float4 r4 = *(const float4*)(res + idx);
        v.x += r4.x; v.y += r4.y; v.z += r4.z; v.w += r4.w;
    }
    if (out)  *(float4*)(out + idx) = v;
    if (out2 && idx + 4 <= out2_lim) *(float4*)(out2 + idx) = v;
    if (tout) whl4(tout, (size_t)m * 2 * N, N, n, v);
}

// ---------------- fused epilogue + layernorm (N=1024; one block per row) ----------------
__global__ void epilogue_ln_kernel(const float* __restrict__ P, const float* __restrict__ bias,
                                   const float* __restrict__ res,
                                   const float* __restrict__ g, const float* __restrict__ be,
                                   float* __restrict__ epi_out, float* __restrict__ ln_out,
                                   __nv_bfloat16* __restrict__ tout,
                                   int M, int kslices)
{
    int m = blockIdx.x, t = threadIdx.x;      // 256 threads, 4 cols each
    __shared__ float red[256];
    int col = t * 4;
    size_t MN = (size_t)M * HH;
    const float* Pm = P + (size_t)m * HH + col;
    float4 v = make_float4(0.f,0.f,0.f,0.f);
    for (int s = 0; s < kslices; s++) {
        float4 p = *(const float4*)(Pm + (size_t)s * MN);
        v.x += p.x; v.y += p.y; v.z += p.z; v.w += p.w;
    }
    float4 b4 = *(const float4*)(bias + col);
    v.x += b4.x; v.y += b4.y; v.z += b4.z; v.w += b4.w;
    if (res) {
        float4 r4 = *(const float4*)(res + (size_t)m * HH + col);
        v.x += r4.x; v.y += r4.y; v.z += r4.z; v.w += r4.w;
    }
    if (epi_out) *(float4*)(epi_out + (size_t)m * HH + col) = v;

    red[t] = v.x + v.y + v.z + v.w; __syncthreads();
    for (int o = 128; o > 0; o >>= 1) { if (t < o) red[t] += red[t+o]; __syncthreads(); }
    float mean = red[0] * (1.f / HH);
    __syncthreads();
    float dx = v.x - mean, dy = v.y - mean, dz = v.z - mean, dw = v.w - mean;
    red[t] = dx*dx + dy*dy + dz*dz + dw*dw; __syncthreads();
    for (int o = 128; o > 0; o >>= 1) { if (t < o) red[t] += red[t+o]; __syncthreads(); }
    float inv = rsqrtf(red[0] * (1.f / HH) + 1e-5f);

    float4 g4 = *(const float4*)(g + col);
    float4 e4 = *(const float4*)(be + col);
    float4 o4;
    o4.x = dx * inv * g4.x + e4.x;
    o4.y = dy * inv * g4.y + e4.y;
    o4.z = dz * inv * g4.z + e4.z;
    o4.w = dw * inv * g4.w + e4.w;
    if (ln_out) *(float4*)(ln_out + (size_t)m * HH + col) = o4;
    whl4(tout, (size_t)m * 2048, 1024, col, o4);
}

// ---------------- fused gelu-epilogue + salience logits ----------------
__global__ void epilogue_logits_kernel(const float* __restrict__ P, const float* __restrict__ bias,
                                       const float* __restrict__ w2, const float* __restrict__ b2,
                                       int M, int kslices)
{
    int m = blockIdx.x, t = threadIdx.x;  // 256
    __shared__ float red[256];
    int col = t * 4;
    size_t MN = (size_t)M * HH;
    const float* Pm = P + (size_t)m * HH + col;
    float4 v = make_float4(0.f,0.f,0.f,0.f);
    for (int s = 0; s < kslices; s++) {
        float4 p = *(const float4*)(Pm + (size_t)s * MN);
        v.x += p.x; v.y += p.y; v.z += p.z; v.w += p.w;
    }
    float4 b4 = *(const float4*)(bias + col);
    v.x = gelu_f(v.x + b4.x); v.y = gelu_f(v.y + b4.y);
    v.z = gelu_f(v.z + b4.z); v.w = gelu_f(v.w + b4.w);
    float4 w = *(const float4*)(w2 + col);
    red[t] = v.x*w.x + v.y*w.y + v.z*w.z + v.w*w.w; __syncthreads();
    for (int o = 128; o > 0; o >>= 1) { if (t < o) red[t] += red[t+o]; __syncthreads(); }
    if (t == 0) g_logits[m] = red[0] + b2[0];
}

// ---------------- small attention: one (b, head) per block; bf16 hi|lo output ----------------
__global__ void attn_kernel(const float* __restrict__ qb, const float* __restrict__ kb,
                            const float* __restrict__ vb, __nv_bfloat16* __restrict__ tout,
                            int NQ, int NK,
                            int qRowStr, long long qBatStr,
                            int kRowStr, long long kBatStr,
                            int vRowStr, long long vBatStr)
{
    int b = blockIdx.x, hd = blockIdx.y;
    const float* q = qb + b * qBatStr + hd * DHD;
    const float* k = kb + b * kBatStr + hd * DHD;
    const float* v = vb + b * vBatStr + hd * DHD;
    __shared__ float qs[16][DHD+1], ks[16][DHD+1], vs[16][DHD+1];
    __shared__ float pr[16][17];
    int t = threadIdx.x;  // 128
    for (int i = 0; i < NQ; i++) qs[i][t] = q[(size_t)i * qRowStr + t];
    for (int i = 0; i < NK; i++) { ks[i][t] = k[(size_t)i * kRowStr + t]; vs[i][t] = v[(size_t)i * vRowStr + t]; }
    __syncthreads();
    const float scale = 0.08838834764831843f;   // 1/sqrt(128)
    for (int p = t; p < NQ * NK; p += 128) {
        int qi = p / NK, ki = p - qi * NK;
        float acc = 0.f;
#pragma unroll 4
        for (int d = 0; d < DHD; d++) acc = fmaf(qs[qi][d], ks[ki][d], acc);
        pr[qi][ki] = acc * scale;
    }
    __syncthreads();
    if (t < NQ) {
        float mx = -1e30f;
        for (int kk = 0; kk < NK; kk++) mx = fmaxf(mx, pr[t][kk]);
        float sm = 0.f;
        for (int kk = 0; kk < NK; kk++) { float e = expf(pr[t][kk] - mx); pr[t][kk] = e; sm += e; }
        float inv = 1.f / sm;
        for (int kk = 0; kk < NK; kk++) pr[t][kk] *= inv;
    }
    __syncthreads();
    for (int j = t; j < NQ * DHD; j += 128) {
        int qi = j >> 7, d = j & 127;
        float acc = 0.f;
        for (int kk = 0; kk < NK; kk++) acc = fmaf(pr[qi][kk], vs[kk][d], acc);
        whl(tout, (size_t)(b * NQ + qi) * 2048, 1024, hd * DHD + d, acc);
    }
}

// ---------------- salience softmax + entropy + weighted segments (bf16 out) ----------------
__global__ void salience_kernel() {
    int b = blockIdx.x, t = threadIdx.x;  // 256
    __shared__ float sal_s[NS];
    if (b == 0 && t == 0) g_red_cnt = 0;    // reset for fused red+finalize
    if (t == 0) {
        float mx = -1e30f;
        for (int s = 0; s < NS; s++) mx = fmaxf(mx, g_logits[b*NS + s]);
        float sm = 0.f;
        for (int s = 0; s < NS; s++) { float e = expf(g_logits[b*NS + s] - mx); sal_s[s] = e; sm += e; }
        float inv = 1.f / sm, ent = 0.f;
        for (int s = 0; s < NS; s++) {
            sal_s[s] *= inv;
            g_sal[b*NS + s] = sal_s[s];
            ent -= sal_s[s] * logf(sal_s[s] + 1e-8f);
        }
        g_entpart[b] = ent;
    }
    __syncthreads();
    for (int i = t; i < NS * HH; i += 256) {
        int s = i >> 10, k = i & 1023;
        float v = g_seg1[(size_t)b * NS * HH + i] * sal_s[s];
        whl(g_bf_wseg, (size_t)(b * NS + s) * 2048, 1024, k, v);
    }
}

// ---------------- redundancy + fused finalize (last block) ----------------
__global__ void red_kernel(float* __restrict__ out, int out_size) {
    int b = blockIdx.x, t = threadIdx.x;  // 128
    __shared__ float ps[NP][HH+1];
    __shared__ float nrm[NP];
    __shared__ float parr[16];
    __shared__ int lastflag;
    for (int i = t; i < NP * HH; i += 128) ps[i >> 10][i & 1023] = g_plan[(size_t)b * NP * HH + i];
    __syncthreads();
    if (t < NP) {
        float s = 0.f;
        for (int d = 0; d < HH; d++) s = fmaf(ps[t][d], ps[t][d], s);
        nrm[t] = fmaxf(sqrtf(s), 1e-12f);
    }
    __syncthreads();
    if (t < 15) {
        int i = 0, j = 0, c = t;
        for (i = 0; i < NP; i++) { int row = NP - 1 - i; if (c < row) { j = i + 1 + c; break; } c -= row; }
        float s = 0.f;
        for (int d = 0; d < HH; d++) s = fmaf(ps[i][d], ps[j][d], s);
        float sim = s / (nrm[i] * nrm[j]);
        parr[t] = 2.f * sim * sim;
    }
    __syncthreads();
    if (t == 0) {
        float s = 0.f;
        for (int p = 0; p < 15; p++) s += parr[p];
        g_redpart[b] = s;
        __threadfence();
        int old = atomicAdd(&g_red_cnt, 1);
        lastflag = (old == NB - 1);
    }
    __syncthreads();
    if (lastflag) {
        for (int i = t; i < NB*NS; i += 128)
            if (PLAN_ELEMS + i < out_size) out[PLAN_ELEMS + i] = g_sal[i];
        if (t == 0) {
            if (PLAN_ELEMS + 256 < out_size) {
                float e = 0.f;
                for (int bb = 0; bb < NB; bb++) e += g_entpart[bb];
                out[PLAN_ELEMS + 256] = e / (float)NB;
            }
            if (PLAN_ELEMS + 257 < out_size) {
                float r = 0.f;
                for (int bb = 0; bb < NB; bb++) r += g_redpart[bb];
                out[PLAN_ELEMS + 257] = r / (float)(NB * NP * (NP - 1));
            }
        }
    }
}

// ---------------- host helpers ----------------
// ks: (K/ks) % 32 == 0; ks*M*N <= partial region size
static void gemm(const __nv_bfloat16* A, const __nv_bfloat16* W, int M, int N, int K, int ks,
                 float* part, cudaStream_t st = 0)
{
    dim3 grid((M + 127) / 128, N / 128, ks);
    gemm_bf16_kernel<<<grid, 256, 2*STGB, st>>>(A, W, part, M, N, K, ks);
}
static void epi(const float* P, const float* bias, const float* res, float* out,
                float* out2, int out2_lim, __nv_bfloat16* tout, int M, int N, int ks, int gelu,
                cudaStream_t st = 0)
{
    int blocks = (M * N + 1023) / 1024;
    epilogue_kernel<<<blocks, 256, 0, st>>>(P, bias, res, out, out2, out2_lim, tout, M, N, ks, gelu);
}

extern "C" void kernel_launch(void* const* d_in, const int* in_sizes, int n_in,
                              void* d_out, int out_size)
{
    const float* ts       = (const float*)d_in[0];
    const int*   mask     = (const int*)  d_in[1];
    const float* sa_in_w  = (const float*)d_in[2];
    const float* sa_in_b  = (const float*)d_in[3];
    const float* sa_out_w = (const float*)d_in[4];
    const float* sa_out_b = (const float*)d_in[5];
    const float* ln_g     = (const float*)d_in[6];
    const float* ln_b     = (const float*)d_in[7];
    const float* sal_w1   = (const float*)d_in[8];
    const float* sal_b1   = (const float*)d_in[9];
    const float* sal_w2   = (const float*)d_in[10];
    const float* sal_b2   = (const float*)d_in[11];
    const float* plan_q   = (const float*)d_in[12];
    const float* qa_in_w  = (const float*)d_in[13];
    const float* qa_in_b  = (const float*)d_in[14];
    const float* qa_out_w = (const float*)d_in[15];
    const float* qa_out_b = (const float*)d_in[16];
    const float* r_in_w   = (const float*)d_in[17];
    const float* r_in_b   = (const float*)d_in[18];
    const float* r_out_w  = (const float*)d_in[19];
    const float* r_out_b  = (const float*)d_in[20];
    const float* r_ln1_g  = (const float*)d_in[21];
    const float* r_ln1_b  = (const float*)d_in[22];
    const float* r_ln2_g  = (const float*)d_in[23];
    const float* r_ln2_b  = (const float*)d_in[24];
    const float* r_w1     = (const float*)d_in[25];
    const float* r_b1     = (const float*)d_in[26];
    const float* r_w2     = (const float*)d_in[27];
    const float* r_b2     = (const float*)d_in[28];
    float* out = (float*)d_out;

    static int init_done = 0;
    static cudaStream_t s2;
    static cudaEvent_t ev_fork, ev_join, ev_q;
    if (!init_done) {
        cudaFuncSetAttribute(gemm_bf16_kernel,
                             cudaFuncAttributeMaxDynamicSharedMemorySize, 2*STGB);
        cudaStreamCreateWithFlags(&s2, cudaStreamNonBlocking);
        cudaEventCreateWithFlags(&ev_fork, cudaEventDisableTiming);
        cudaEventCreateWithFlags(&ev_join, cudaEventDisableTiming);
        cudaEventCreateWithFlags(&ev_q, cudaEventDisableTiming);
        init_done = 1;
    }

    float *p_part, *p_qkv, *p_seg1, *p_qh, *p_kv, *p_plan, *p_qkvr, *p_seg0;
    cudaGetSymbolAddress((void**)&p_part, g_part);
    cudaGetSymbolAddress((void**)&p_seg0, g_seg0);
    cudaGetSymbolAddress((void**)&p_qkv,  g_qkv);
    cudaGetSymbolAddress((void**)&p_seg1, g_seg1);
    cudaGetSymbolAddress((void**)&p_qh,   g_qh);
    cudaGetSymbolAddress((void**)&p_kv,   g_kv);
    cudaGetSymbolAddress((void**)&p_plan, g_plan);
    cudaGetSymbolAddress((void**)&p_qkvr, g_qkvr);

    __nv_bfloat16 *t_seg0, *t_o, *t_seg1, *t_wseg, *t_pq, *t_o2, *t_y, *t_o3, *t_ffn, *wbf;
    cudaGetSymbolAddress((void**)&t_seg0, g_bf_seg0);
    cudaGetSymbolAddress((void**)&t_o,    g_bf_o);
    cudaGetSymbolAddress((void**)&t_seg1, g_bf_seg1);
    cudaGetSymbolAddress((void**)&t_wseg, g_bf_wseg);
    cudaGetSymbolAddress((void**)&t_pq,   g_bf_pq);
    cudaGetSymbolAddress((void**)&t_o2,   g_bf_o2);
    cudaGetSymbolAddress((void**)&t_y,    g_bf_y);
    cudaGetSymbolAddress((void**)&t_o3,   g_bf_o3);
    cudaGetSymbolAddress((void**)&t_ffn,  g_bf_ffn);
    cudaGetSymbolAddress((void**)&wbf,    g_wbf);

    // 0) weight conversion + qh projection chain forked onto side stream
    CvtTab tab;
    tab.src[0]=sa_in_w;  tab.dst[0]=wbf+WOFF_SAIN;  tab.n[0]=3145728; tab.logK[0]=10;
    tab.src[1]=sa_out_w; tab.dst[1]=wbf+WOFF_SAOUT; tab.n[1]=1048576; tab.logK[1]=10;
    tab.src[2]=sal_w1;   tab.dst[2]=wbf+WOFF_SAL1;  tab.n[2]=1048576; tab.logK[2]=10;
    tab.src[3]=qa_in_w;  tab.dst[3]=wbf+WOFF_QAIN;  tab.n[3]=3145728; tab.logK[3]=10;
    tab.src[4]=qa_out_w; tab.dst[4]=wbf+WOFF_QAOUT; tab.n[4]=1048576; tab.logK[4]=10;
    tab.src[5]=r_in_w;   tab.dst[5]=wbf+WOFF_RIN;   tab.n[5]=6291456; tab.logK[5]=10;
    tab.src[6]=r_out_w;  tab.dst[6]=wbf+WOFF_ROUT;  tab.n[6]=2097152; tab.logK[6]=10;
    tab.src[7]=r_w1;     tab.dst[7]=wbf+WOFF_RW1;   tab.n[7]=8388608; tab.logK[7]=10;
    tab.src[8]=r_w2;     tab.dst[8]=wbf+WOFF_RW2;   tab.n[8]=8388608; tab.logK[8]=12;
    tab.src[9]=plan_q;   tab.dst[9]=t_pq;           tab.n[9]=6144;    tab.logK[9]=10;

    cudaEventRecord(ev_fork, 0);
    cudaStreamWaitEvent(s2, ev_fork, 0);
    convert_kernel<<<dim3(2048, 10), 256, 0, s2>>>(tab);
    cudaEventRecord(ev_join, s2);
    // qh projection: depends only on converted weights; own partial region (+7M)
    gemm(t_pq, wbf+WOFF_QAIN, NP, HH, HH, 32, p_part + 7*1024*1024, s2);
    epi(p_part + 7*1024*1024, qa_in_b, nullptr, p_qh, nullptr, 0, nullptr, NP, HH, 32, 0, s2);
    cudaEventRecord(ev_q, s2);

    // 1) lengths + bounds, fused segment pooling (main stream, overlaps convert)
    lengths_kernel<<<16, 256>>>(mask);
    segpool_kernel<<<NB*NS, 256>>>(ts);

    // join: GEMMs below need converted weights
    cudaStreamWaitEvent(0, ev_join, 0);

    // 2) segment self-attention
    gemm(t_seg0, wbf+WOFF_SAIN, 256, 3*HH, HH, 8, p_part);
    epi(p_part, sa_in_b, nullptr, p_qkv, nullptr, 0, nullptr, 256, 3*HH, 8, 0);
    attn_kernel<<<dim3(NB, NHEAD), 128>>>(p_qkv, p_qkv + HH, p_qkv + 2*HH, t_o,
                                          16, 16,
                                          3*HH, (long long)NS*3*HH,
                                          3*HH, (long long)NS*3*HH,
                                          3*HH, (long long)NS*3*HH);
    gemm(t_o, wbf+WOFF_SAOUT, 256, HH, HH, 16, p_part);
    epilogue_ln_kernel<<<256, 256>>>(p_part, sa_out_b, p_seg0, ln_g, ln_b,
                                     nullptr, p_seg1, t_seg1, 256, 16);

    // 3) salience (gelu-epilogue + logits fused)
    gemm(t_seg1, wbf+WOFF_SAL1, 256, HH, HH, 16, p_part);
    epilogue_logits_kernel<<<256, 256>>>(p_part, sal_b1, sal_w2, sal_b2, 256, 16);
    salience_kernel<<<16, 256>>>();

    // 4) plan cross-attention (qh computed on side stream)
    gemm(t_wseg, wbf+WOFF_QAIN + (size_t)HH*2*HH, 256, 2*HH, HH, 8, p_part);
    epi(p_part, qa_in_b + HH, nullptr, p_kv, nullptr, 0, nullptr, 256, 2*HH, 8, 0);
    cudaStreamWaitEvent(0, ev_q, 0);
    attn_kernel<<<dim3(NB, NHEAD), 128>>>(p_qh, p_kv, p_kv + HH, t_o2,
                                          NP, 16,
                                          HH,   0LL,
                                          2*HH, (long long)NS*2*HH,
                                          2*HH, (long long)NS*2*HH);
    gemm(t_o2, wbf+WOFF_QAOUT, NB*NP, HH, HH, 16, p_part);
    epilogue_ln_kernel<<<NB*NP, 256>>>(p_part, qa_out_b, nullptr, r_ln1_g, r_ln1_b,
                                       p_plan, nullptr, t_y, NB*NP, 16);

    // 5) refinement transformer layers (norm_first)
    for (int l = 0; l < 2; l++) {
        gemm(t_y, wbf+WOFF_RIN + (size_t)l*6291456, NB*NP, 3*HH, HH, 8, p_part);
        epi(p_part, r_in_b + l*3*HH, nullptr, p_qkvr, nullptr, 0, nullptr, NB*NP, 3*HH, 8, 0);
        attn_kernel<<<dim3(NB, NHEAD), 128>>>(p_qkvr, p_qkvr + HH, p_qkvr + 2*HH, t_o3,
                                              NP, NP,
                                              3*HH, (long long)NP*3*HH,
                                              3*HH, (long long)NP*3*HH,
                                              3*HH, (long long)NP*3*HH);
        gemm(t_o3, wbf+WOFF_ROUT + (size_t)l*2097152, NB*NP, HH, HH, 16, p_part);
        epilogue_ln_kernel<<<NB*NP, 256>>>(p_part, r_out_b + l*HH, p_plan,
                                           r_ln2_g + l*HH, r_ln2_b + l*HH,
                                           p_plan, nullptr, t_y, NB*NP, 16);
        gemm(t_y, wbf+WOFF_RW1 + (size_t)l*8388608, NB*NP, 4*HH, HH, 8, p_part);
        epi(p_part, r_b1 + l*4*HH, nullptr, nullptr, nullptr, 0, t_ffn, NB*NP, 4*HH, 8, 1);
        gemm(t_ffn, wbf+WOFF_RW2 + (size_t)l*8388608, NB*NP, HH, 4*HH, 32, p_part);
        if (l == 0) {
            epilogue_ln_kernel<<<NB*NP, 256>>>(p_part, r_b2, p_plan,
                                               r_ln1_g + HH, r_ln1_b + HH,
                                               p_plan, nullptr, t_y, NB*NP, 32);
        } else {
            int lim = out_size < PLAN_ELEMS ? out_size : PLAN_ELEMS;
            epi(p_part, r_b2 + HH, p_plan, p_plan, out, lim, nullptr, NB*NP, HH, 32, 0);
        }
    }

    // 6) redundancy + finalize (fused)
    red_kernel<<<16, 128>>>(out, out_size);
}

// round 17
// speedup vs baseline: 1.2139x; 1.0351x over previous
#include <cuda_runtime.h>
#include <cuda_bf16.h>
#include <math.h>

// ---------------- problem constants ----------------
#define NB 16      // batch
#define NT 4096    // tokens
#define HH 1024    // hidden
#define NS 16      // segments
#define NP 6       // plan slots
#define NHEAD 8
#define DHD 128    // head dim
#define PLAN_ELEMS (NB*NP*HH)   // 98304

// ---------------- device scratch (static, no allocs) ----------------
__device__ float g_seg0[NB*NS*HH];
__device__ float g_qkv[NB*NS*3*HH];
__device__ float g_seg1[NB*NS*HH];
__device__ float g_logits[NB*NS];
__device__ float g_sal[NB*NS];
__device__ float g_qh[NP*HH];
__device__ float g_kv[NB*NS*2*HH];
__device__ float g_plan[NB*NP*HH];
__device__ float g_qkvr[NB*NP*3*HH];
__device__ float g_part[8*1024*1024];          // split-K partials (32MB); qh region at +7M
__device__ float g_entpart[NB];
__device__ float g_redpart[NB];
__device__ int   g_red_cnt;

// bf16 [hi(K)|lo(K)] operand buffers
__device__ __nv_bfloat16 g_bf_seg0[256*2048];
__device__ __nv_bfloat16 g_bf_o   [256*2048];
__device__ __nv_bfloat16 g_bf_seg1[256*2048];
__device__ __nv_bfloat16 g_bf_wseg[256*2048];
__device__ __nv_bfloat16 g_bf_pq  [NP*2048];
__device__ __nv_bfloat16 g_bf_o2  [96*2048];
__device__ __nv_bfloat16 g_bf_y   [96*2048];
__device__ __nv_bfloat16 g_bf_o3  [96*2048];
__device__ __nv_bfloat16 g_bf_ffn [96*8192];
__device__ __nv_bfloat16 g_wbf[69206016];      // all weights hi|lo (138MB)

// weight offsets into g_wbf (bf16 elems)
#define WOFF_SAIN   0LL
#define WOFF_SAOUT  6291456LL
#define WOFF_SAL1   8388608LL
#define WOFF_QAIN   10485760LL
#define WOFF_QAOUT  16777216LL
#define WOFF_RIN    18874368LL
#define WOFF_ROUT   31457280LL
#define WOFF_RW1    35651584LL
#define WOFF_RW2    52428800LL

// ---------------- helpers ----------------
__device__ __forceinline__ unsigned smem_u32(const void* p) {
    unsigned a;
    asm("{ .reg .u64 t; cvta.to.shared.u64 t, %1; cvt.u32.u64 %0, t; }" : "=r"(a) : "l"(p));
    return a;
}
__device__ __forceinline__ unsigned pack_pair(float f0, float f1, bool lo) {
    if (lo) {
        f0 = f0 - __bfloat162float(__float2bfloat16(f0));
        f1 = f1 - __bfloat162float(__float2bfloat16(f1));
    }
    __nv_bfloat162 p = __floats2bfloat162_rn(f0, f1);
    return *reinterpret_cast<unsigned*>(&p);
}
__device__ __forceinline__ void cp16(unsigned dst, const void* src, int sz) {
    asm volatile("cp.async.ca.shared.global [%0], [%1], 16, %2;"
                 :: "r"(dst), "l"(src), "r"(sz));
}
__device__ __forceinline__ void whl(__nv_bfloat16* t, size_t rowbase, int K, int k, float v) {
    __nv_bfloat16 h = __float2bfloat16(v);
    __nv_bfloat16 l = __float2bfloat16(v - __bfloat162float(h));
    t[rowbase + k] = h;
    t[rowbase + K + k] = l;
}
__device__ __forceinline__ void whl4(__nv_bfloat16* t, size_t rowbase, int N, int col, float4 v) {
    unsigned h0 = pack_pair(v.x, v.y, false), h1 = pack_pair(v.z, v.w, false);
    unsigned l0 = pack_pair(v.x, v.y, true),  l1 = pack_pair(v.z, v.w, true);
    __nv_bfloat16* tr = t + rowbase + col;
    *(uint2*)tr       = make_uint2(h0, h1);
    *(uint2*)(tr + N) = make_uint2(l0, l1);
}
__device__ __forceinline__ float gelu_f(float v) {
    return 0.5f * v * (1.f + erff(v * 0.70710678118654752f));
}

// ---------------- weight conversion (all tensors, one launch) ----------------
struct CvtTab {
    const float* src[10];
    __nv_bfloat16* dst[10];
    int n[10];
    int logK[10];
};
__global__ void convert_kernel(CvtTab tab) {
    int tsel = blockIdx.y;
    const float* s = tab.src[tsel];
    __nv_bfloat16* d = tab.dst[tsel];
    long long n = tab.n[tsel];
    int logK = tab.logK[tsel];
    int K = 1 << logK;
    long long stride = (long long)gridDim.x * blockDim.x * 4;
    for (long long idx = ((long long)blockIdx.x * blockDim.x + threadIdx.x) * 4;
         idx < n; idx += stride) {
        float4 v = *(const float4*)(s + idx);
        int k = (int)(idx & (K - 1));
        long long row = idx >> logK;
        __nv_bfloat16* dr = d + row * (2LL * K) + k;
        unsigned h0 = pack_pair(v.x, v.y, false), h1 = pack_pair(v.z, v.w, false);
        unsigned l0 = pack_pair(v.x, v.y, true),  l1 = pack_pair(v.z, v.w, true);
        *(uint2*)dr       = make_uint2(h0, h1);
        *(uint2*)(dr + K) = make_uint2(l0, l1);
    }
}

// ---------------- fused segment pooling (computes its own length bounds) ----------------
__global__ void segpool_kernel(const float* __restrict__ ts, const int* __restrict__ mask) {
    int seg = blockIdx.x;                 // 0..255
    int b = seg >> 4, s = seg & 15;
    int t = threadIdx.x;                  // 256 threads
    __shared__ int redi[256];

    // inline length: sum this batch's mask row (int4 loads, 16 ints/thread)
    const int4* m4 = (const int4*)(mask + (size_t)b * NT);
    int acc = 0;
#pragma unroll
    for (int i = 0; i < 4; i++) {
        int4 v = m4[t + i * 256];
        acc += v.x + v.y + v.z + v.w;
    }
    redi[t] = acc; __syncthreads();
    for (int o = 128; o > 0; o >>= 1) { if (t < o) redi[t] += redi[t+o]; __syncthreads(); }
    int L = redi[0];
    int lo = (s * L) / NS, hi = ((s + 1) * L) / NS;
    int cnt = hi - lo;

    const float* base = ts + (size_t)b * NT * HH + t * 4;
    float4 a[8];
#pragma unroll
    for (int i = 0; i < 8; i++) a[i] = make_float4(0.f,0.f,0.f,0.f);
    int r = lo;
    for (; r + 8 <= hi; r += 8) {
#pragma unroll
        for (int i = 0; i < 8; i++) {
            float4 v = *(const float4*)(base + (size_t)(r+i) * HH);
            a[i].x += v.x; a[i].y += v.y; a[i].z += v.z; a[i].w += v.w;
        }
    }
    for (; r < hi; r++) {
        float4 v = *(const float4*)(base + (size_t)r * HH);
        a[0].x += v.x; a[0].y += v.y; a[0].z += v.z; a[0].w += v.w;
    }
#pragma unroll
    for (int i = 1; i < 8; i++) {
        a[0].x += a[i].x; a[0].y += a[i].y; a[0].z += a[i].z; a[0].w += a[i].w;
    }
    float inv = 1.f / fmaxf((float)cnt, 1.f);
    float4 v = make_float4(a[0].x * inv, a[0].y * inv, a[0].z * inv, a[0].w * inv);
    *(float4*)&g_seg0[(size_t)seg * HH + t*4] = v;
    whl4(g_bf_seg0, (size_t)seg * 2048, 1024, t*4, v);
}

// ---------------- bf16 split-K GEMM (compensated, fragment-reuse, cp.async 2-stage) ----------------
// D = A_hi*W_hi + A_lo*W_hi + A_hi*W_lo.  A,W stored [rows, 2K] = [hi(K)|lo(K)].
// 128x128 tile, BK=32, 256 thr, 8 warps 64x32. Per k16 step: load af_hi/af_lo/bf_hi/bf_lo
// fragments ONCE, run the 3 phase mma groups from registers.
#define SA 40   // padded smem row stride (bf16) => 80B
#define MATB (128*SA*2)        // 10240 bytes per tile
#define STGB (4*MATB)          // 40960 bytes per stage

__global__ void __launch_bounds__(256) gemm_bf16_kernel(
    const __nv_bfloat16* __restrict__ A, const __nv_bfloat16* __restrict__ W,
    float* __restrict__ P, int M, int N, int K, int kslices)
{
    extern __shared__ __align__(16) unsigned char smem[];
    int tid = threadIdx.x, wid = tid >> 5, lane = tid & 31;
    int m0 = blockIdx.x * 128, n0 = blockIdx.y * 128;
    int K2 = 2 * K;
    int Kper = K / kslices, kstart = blockIdx.z * Kper, nch = Kper >> 5;
    int wm = (wid & 1) * 64, wn = (wid >> 1) * 32;
    unsigned sm = smem_u32(smem);

    int r0 = tid >> 2, s0 = tid & 3;
    int f1 = tid + 256, r1 = f1 >> 2, s1 = f1 & 3;
    int szA0 = (m0 + r0 < M) ? 16 : 0, szA1 = (m0 + r1 < M) ? 16 : 0;
    const __nv_bfloat16* a0 = A + (size_t)(szA0 ? (m0 + r0) : 0) * K2 + s0 * 8;
    const __nv_bfloat16* a1 = A + (size_t)(szA1 ? (m0 + r1) : 0) * K2 + s1 * 8;
    const __nv_bfloat16* w0 = W + (size_t)(n0 + r0) * K2 + s0 * 8;
    const __nv_bfloat16* w1 = W + (size_t)(n0 + r1) * K2 + s1 * 8;
    unsigned o0 = (unsigned)(r0*SA + s0*8)*2, o1 = (unsigned)(r1*SA + s1*8)*2;

#define LOAD_STAGE(c, st) { \
    int kb = kstart + (c)*32; \
    unsigned so = sm + (unsigned)(st) * STGB; \
    cp16(so + o0,          a0 + kb,     szA0); cp16(so + o1,          a1 + kb,     szA1); \
    cp16(so + MATB + o0,   a0 + K + kb, szA0); cp16(so + MATB + o1,   a1 + K + kb, szA1); \
    cp16(so + 2*MATB + o0, w0 + kb,     16);   cp16(so + 2*MATB + o1, w1 + kb,     16); \
    cp16(so + 3*MATB + o0, w0 + K + kb, 16);   cp16(so + 3*MATB + o1, w1 + K + kb, 16); \
    asm volatile("cp.async.commit_group;"); }

    float acc[4][4][4];
#pragma unroll
    for (int a = 0; a < 4; a++)
#pragma unroll
        for (int b = 0; b < 4; b++)
#pragma unroll
            for (int c = 0; c < 4; c++) acc[a][b][c] = 0.f;

    LOAD_STAGE(0, 0);

    int g = lane >> 3, r = lane & 7;
    for (int c = 0; c < nch; c++) {
        if (c + 1 < nch) {
            LOAD_STAGE(c + 1, (c + 1) & 1);
            asm volatile("cp.async.wait_group 1;");
        } else {
            asm volatile("cp.async.wait_group 0;");
        }
        __syncthreads();
        unsigned st = sm + (unsigned)(c & 1) * STGB;
#pragma unroll
        for (int ks = 0; ks < 2; ks++) {
            unsigned afh[4][4], afl[4][4], bfh[4][2], bfl[4][2];
#pragma unroll
            for (int mt = 0; mt < 4; mt++) {
                unsigned roff = (unsigned)(((wm + mt*16 + (g & 1)*8 + r) * SA
                                   + ks*16 + (g >> 1)*8) * 2);
                asm volatile("ldmatrix.sync.aligned.m8n8.x4.shared.b16 {%0,%1,%2,%3}, [%4];"
                    : "=r"(afh[mt][0]), "=r"(afh[mt][1]), "=r"(afh[mt][2]), "=r"(afh[mt][3])
                    : "r"(st + roff));
                asm volatile("ldmatrix.sync.aligned.m8n8.x4.shared.b16 {%0,%1,%2,%3}, [%4];"
                    : "=r"(afl[mt][0]), "=r"(afl[mt][1]), "=r"(afl[mt][2]), "=r"(afl[mt][3])
                    : "r"(st + MATB + roff));
            }
#pragma unroll
            for (int np = 0; np < 2; np++) {
                unsigned roff = (unsigned)(((wn + np*16 + (g >> 1)*8 + r) * SA
                                   + ks*16 + (g & 1)*8) * 2);
                unsigned t0,t1,t2,t3;
                asm volatile("ldmatrix.sync.aligned.m8n8.x4.shared.b16 {%0,%1,%2,%3}, [%4];"
                    : "=r"(t0), "=r"(t1), "=r"(t2), "=r"(t3) : "r"(st + 2u*MATB + roff));
                bfh[2*np][0] = t0; bfh[2*np][1] = t1;
                bfh[2*np+1][0] = t2; bfh[2*np+1][1] = t3;
                asm volatile("ldmatrix.sync.aligned.m8n8.x4.shared.b16 {%0,%1,%2,%3}, [%4];"
                    : "=r"(t0), "=r"(t1), "=r"(t2), "=r"(t3) : "r"(st + 3u*MATB + roff));
                bfl[2*np][0] = t0; bfl[2*np][1] = t1;
                bfl[2*np+1][0] = t2; bfl[2*np+1][1] = t3;
            }
#define MMA16(AF, BF) \
_Pragma("unroll") \
            for (int mt = 0; mt < 4; mt++) \
_Pragma("unroll") \
                for (int nt = 0; nt < 4; nt++) { \
                    asm volatile( \
                        "mma.sync.aligned.m16n8k16.row.col.f32.bf16.bf16.f32 " \
                        "{%0,%1,%2,%3}, {%4,%5,%6,%7}, {%8,%9}, {%0,%1,%2,%3};" \
                        : "+f"(acc[mt][nt][0]), "+f"(acc[mt][nt][1]), \
                          "+f"(acc[mt][nt][2]), "+f"(acc[mt][nt][3]) \
                        : "r"(AF[mt][0]), "r"(AF[mt][1]), "r"(AF[mt][2]), "r"(AF[mt][3]), \
                          "r"(BF[nt][0]), "r"(BF[nt][1])); \
                }
            MMA16(afh, bfh)
            MMA16(afl, bfh)
            MMA16(afh, bfl)
#undef MMA16
        }
        __syncthreads();
    }

    size_t base = (size_t)blockIdx.z * M * N;
#pragma unroll
    for (int mt = 0; mt < 4; mt++) {
        int m = m0 + wm + mt*16 + (lane >> 2);
#pragma unroll
        for (int nt = 0; nt < 4; nt++) {
            int n = n0 + wn + nt*8 + (lane & 3)*2;
            if (m < M)
                *(float2*)(P + base + (size_t)m * N + n)
                    = make_float2(acc[mt][nt][0], acc[mt][nt][1]);
            if (m + 8 < M)
                *(float2*)(P + base + (size_t)(m+8) * N + n)
                    = make_float2(acc[mt][nt][2], acc[mt][nt][3]);
        }
    }
#undef LOAD_STAGE
}

// ---------------- plain epilogue (vectorized) ----------------
__global__ void epilogue_kernel(const float* __restrict__ P, const float* __restrict__ bias,
                                const float* __restrict__ res, float* __restrict__ out,
                                float* __restrict__ out2, int out2_lim,
                                __nv_bfloat16* __restrict__ tout,
                                int M, int N, int kslices, int gelu)
{
    int idx = (blockIdx.x * 256 + threadIdx.x) * 4;
    if (idx >= M * N) return;
    int n = idx % N, m = idx / N;
    size_t MN = (size_t)M * N;
    float4 v = make_float4(0.f,0.f,0.f,0.f);
    for (int s = 0; s < kslices; s++) {
        float4 p = *(const float4*)(P + (size_t)s * MN + idx);
        v.x += p.x; v.y += p.y; v.z += p.z; v.w += p.w;
    }
    float4 b4 = *(const float4*)(bias + n);
    v.x += b4.x; v.y += b4.y; v.z += b4.z; v.w += b4.w;
    if (gelu) { v.x = gelu_f(v.x); v.y = gelu_f(v.y); v.z = gelu_f(v.z); v.w = gelu_f(v.w); }
    if (res) {
        float4 r4 = *(const float4*)(res + idx);
        v.x += r4.x; v.y += r4.y; v.z += r4.z; v.w += r4.w;
    }
    if (out)  *(float4*)(out + idx) = v;
    if (out2 && idx + 4 <= out2_lim) *(float4*)(out2 + idx) = v;
    if (tout) whl4(tout, (size_t)m * 2 * N, N, n, v);
}

// ---------------- fused epilogue + layernorm (N=1024; one block per row) ----------------
__global__ void epilogue_ln_kernel(const float* __restrict__ P, const float* __restrict__ bias,
                                   const float* __restrict__ res,
                                   const float* __restrict__ g, const float* __restrict__ be,
                                   float* __restrict__ epi_out, float* __restrict__ ln_out,
                                   __nv_bfloat16* __restrict__ tout,
                                   int M, int kslices)
{
    int m = blockIdx.x, t = threadIdx.x;      // 256 threads, 4 cols each
    __shared__ float red[256];
    int col = t * 4;
    size_t MN = (size_t)M * HH;
    const float* Pm = P + (size_t)m * HH + col;
    float4 v = make_float4(0.f,0.f,0.f,0.f);
    for (int s = 0; s < kslices; s++) {
        float4 p = *(const float4*)(Pm + (size_t)s * MN);
        v.x += p.x; v.y += p.y; v.z += p.z; v.w += p.w;
    }
    float4 b4 = *(const float4*)(bias + col);
    v.x += b4.x; v.y += b4.y; v.z += b4.z; v.w += b4.w;
    if (res) {
        float4 r4 = *(const float4*)(res + (size_t)m * HH + col);
        v.x += r4.x; v.y += r4.y; v.z += r4.z; v.w += r4.w;
    }
    if (epi_out) *(float4*)(epi_out + (size_t)m * HH + col) = v;

    red[t] = v.x + v.y + v.z + v.w; __syncthreads();
    for (int o = 128; o > 0; o >>= 1) { if (t < o) red[t] += red[t+o]; __syncthreads(); }
    float mean = red[0] * (1.f / HH);
    __syncthreads();
    float dx = v.x - mean, dy = v.y - mean, dz = v.z - mean, dw = v.w - mean;
    red[t] = dx*dx + dy*dy + dz*dz + dw*dw; __syncthreads();
    for (int o = 128; o > 0; o >>= 1) { if (t < o) red[t] += red[t+o]; __syncthreads(); }
    float inv = rsqrtf(red[0] * (1.f / HH) + 1e-5f);

    float4 g4 = *(const float4*)(g + col);
    float4 e4 = *(const float4*)(be + col);
    float4 o4;
    o4.x = dx * inv * g4.x + e4.x;
    o4.y = dy * inv * g4.y + e4.y;
    o4.z = dz * inv * g4.z + e4.z;
    o4.w = dw * inv * g4.w + e4.w;
    if (ln_out) *(float4*)(ln_out + (size_t)m * HH + col) = o4;
    whl4(tout, (size_t)m * 2048, 1024, col, o4);
}

// ---------------- fused gelu-epilogue + salience logits ----------------
__global__ void epilogue_logits_kernel(const float* __restrict__ P, const float* __restrict__ bias,
                                       const float* __restrict__ w2, const float* __restrict__ b2,
                                       int M, int kslices)
{
    int m = blockIdx.x, t = threadIdx.x;  // 256
    __shared__ float red[256];
    int col = t * 4;
    size_t MN = (size_t)M * HH;
    const float* Pm = P + (size_t)m * HH + col;
    float4 v = make_float4(0.f,0.f,0.f,0.f);
    for (int s = 0; s < kslices; s++) {
        float4 p = *(const float4*)(Pm + (size_t)s * MN);
        v.x += p.x; v.y += p.y; v.z += p.z; v.w += p.w;
    }
    float4 b4 = *(const float4*)(bias + col);
    v.x = gelu_f(v.x + b4.x); v.y = gelu_f(v.y + b4.y);
    v.z = gelu_f(v.z + b4.z); v.w = gelu_f(v.w + b4.w);
    float4 w = *(const float4*)(w2 + col);
    red[t] = v.x*w.x + v.y*w.y + v.z*w.z + v.w*w.w; __syncthreads();
    for (int o = 128; o > 0; o >>= 1) { if (t < o) red[t] += red[t+o]; __syncthreads(); }
    if (t == 0) g_logits[m] = red[0] + b2[0];
}

// ---------------- small attention: one (b, head) per block; bf16 hi|lo output ----------------
__global__ void attn_kernel(const float* __restrict__ qb, const float* __restrict__ kb,
                            const float* __restrict__ vb, __nv_bfloat16* __restrict__ tout,
                            int NQ, int NK,
                            int qRowStr, long long qBatStr,
                            int kRowStr, long long kBatStr,
                            int vRowStr, long long vBatStr)
{
    int b = blockIdx.x, hd = blockIdx.y;
    const float* q = qb + b * qBatStr + hd * DHD;
    const float* k = kb + b * kBatStr + hd * DHD;
    const float* v = vb + b * vBatStr + hd * DHD;
    __shared__ float qs[16][DHD+1], ks[16][DHD+1], vs[16][DHD+1];
    __shared__ float pr[16][17];
    int t = threadIdx.x;  // 128
    for (int i = 0; i < NQ; i++) qs[i][t] = q[(size_t)i * qRowStr + t];
    for (int i = 0; i < NK; i++) { ks[i][t] = k[(size_t)i * kRowStr + t]; vs[i][t] = v[(size_t)i * vRowStr + t]; }
    __syncthreads();
    const float scale = 0.08838834764831843f;   // 1/sqrt(128)
    for (int p = t; p < NQ * NK; p += 128) {
        int qi = p / NK, ki = p - qi * NK;
        float acc = 0.f;
#pragma unroll 4
        for (int d = 0; d < DHD; d++) acc = fmaf(qs[qi][d], ks[ki][d], acc);
        pr[qi][ki] = acc * scale;
    }
    __syncthreads();
    if (t < NQ) {
        float mx = -1e30f;
        for (int kk = 0; kk < NK; kk++) mx = fmaxf(mx, pr[t][kk]);
        float sm = 0.f;
        for (int kk = 0; kk < NK; kk++) { float e = expf(pr[t][kk] - mx); pr[t][kk] = e; sm += e; }
        float inv = 1.f / sm;
        for (int kk = 0; kk < NK; kk++) pr[t][kk] *= inv;
    }
    __syncthreads();
    for (int j = t; j < NQ * DHD; j += 128) {
        int qi = j >> 7, d = j & 127;
        float acc = 0.f;
        for (int kk = 0; kk < NK; kk++) acc = fmaf(pr[qi][kk], vs[kk][d], acc);
        whl(tout, (size_t)(b * NQ + qi) * 2048, 1024, hd * DHD + d, acc);
    }
}

// ---------------- salience softmax + entropy + weighted segments (bf16 out) ----------------
__global__ void salience_kernel() {
    int b = blockIdx.x, t = threadIdx.x;  // 256
    __shared__ float sal_s[NS];
    if (b == 0 && t == 0) g_red_cnt = 0;    // reset for fused red+finalize
    if (t == 0) {
        float mx = -1e30f;
        for (int s = 0; s < NS; s++) mx = fmaxf(mx, g_logits[b*NS + s]);
        float sm = 0.f;
        for (int s = 0; s < NS; s++) { float e = expf(g_logits[b*NS + s] - mx); sal_s[s] = e; sm += e; }
        float inv = 1.f / sm, ent = 0.f;
        for (int s = 0; s < NS; s++) {
            sal_s[s] *= inv;
            g_sal[b*NS + s] = sal_s[s];
            ent -= sal_s[s] * logf(sal_s[s] + 1e-8f);
        }
        g_entpart[b] = ent;
    }
    __syncthreads();
    for (int i = t; i < NS * HH; i += 256) {
        int s = i >> 10, k = i & 1023;
        float v = g_seg1[(size_t)b * NS * HH + i] * sal_s[s];
        whl(g_bf_wseg, (size_t)(b * NS + s) * 2048, 1024, k, v);
    }
}

// ---------------- redundancy + fused finalize (last block) ----------------
__global__ void red_kernel(float* __restrict__ out, int out_size) {
    int b = blockIdx.x, t = threadIdx.x;  // 128
    __shared__ float ps[NP][HH+1];
    __shared__ float nrm[NP];
    __shared__ float parr[16];
    __shared__ int lastflag;
    for (int i = t; i < NP * HH; i += 128) ps[i >> 10][i & 1023] = g_plan[(size_t)b * NP * HH + i];
    __syncthreads();
    if (t < NP) {
        float s = 0.f;
        for (int d = 0; d < HH; d++) s = fmaf(ps[t][d], ps[t][d], s);
        nrm[t] = fmaxf(sqrtf(s), 1e-12f);
    }
    __syncthreads();
    if (t < 15) {
        int i = 0, j = 0, c = t;
        for (i = 0; i < NP; i++) { int row = NP - 1 - i; if (c < row) { j = i + 1 + c; break; } c -= row; }
        float s = 0.f;
        for (int d = 0; d < HH; d++) s = fmaf(ps[i][d], ps[j][d], s);
        float sim = s / (nrm[i] * nrm[j]);
        parr[t] = 2.f * sim * sim;
    }
    __syncthreads();
    if (t == 0) {
        float s = 0.f;
        for (int p = 0; p < 15; p++) s += parr[p];
        g_redpart[b] = s;
        __threadfence();
        int old = atomicAdd(&g_red_cnt, 1);
        lastflag = (old == NB - 1);
    }
    __syncthreads();
    if (lastflag) {
        for (int i = t; i < NB*NS; i += 128)
            if (PLAN_ELEMS + i < out_size) out[PLAN_ELEMS + i] = g_sal[i];
        if (t == 0) {
            if (PLAN_ELEMS + 256 < out_size) {
                float e = 0.f;
                for (int bb = 0; bb < NB; bb++) e += g_entpart[bb];
                out[PLAN_ELEMS + 256] = e / (float)NB;
            }
            if (PLAN_ELEMS + 257 < out_size) {
                float r = 0.f;
                for (int bb = 0; bb < NB; bb++) r += g_redpart[bb];
                out[PLAN_ELEMS + 257] = r / (float)(NB * NP * (NP - 1));
            }
        }
    }
}

// ---------------- host helpers ----------------
// ks: (K/ks) % 32 == 0; ks*M*N <= partial region size
static void gemm(const __nv_bfloat16* A, const __nv_bfloat16* W, int M, int N, int K, int ks,
                 float* part, cudaStream_t st = 0)
{
    dim3 grid((M + 127) / 128, N / 128, ks);
    gemm_bf16_kernel<<<grid, 256, 2*STGB, st>>>(A, W, part, M, N, K, ks);
}
static void epi(const float* P, const float* bias, const float* res, float* out,
                float* out2, int out2_lim, __nv_bfloat16* tout, int M, int N, int ks, int gelu,
                cudaStream_t st = 0)
{
    int blocks = (M * N + 1023) / 1024;
    epilogue_kernel<<<blocks, 256, 0, st>>>(P, bias, res, out, out2, out2_lim, tout, M, N, ks, gelu);
}

extern "C" void kernel_launch(void* const* d_in, const int* in_sizes, int n_in,
                              void* d_out, int out_size)
{
    const float* ts       = (const float*)d_in[0];
    const int*   mask     = (const int*)  d_in[1];
    const float* sa_in_w  = (const float*)d_in[2];
    const float* sa_in_b  = (const float*)d_in[3];
    const float* sa_out_w = (const float*)d_in[4];
    const float* sa_out_b = (const float*)d_in[5];
    const float* ln_g     = (const float*)d_in[6];
    const float* ln_b     = (const float*)d_in[7];
    const float* sal_w1   = (const float*)d_in[8];
    const float* sal_b1   = (const float*)d_in[9];
    const float* sal_w2   = (const float*)d_in[10];
    const float* sal_b2   = (const float*)d_in[11];
    const float* plan_q   = (const float*)d_in[12];
    const float* qa_in_w  = (const float*)d_in[13];
    const float* qa_in_b  = (const float*)d_in[14];
    const float* qa_out_w = (const float*)d_in[15];
    const float* qa_out_b = (const float*)d_in[16];
    const float* r_in_w   = (const float*)d_in[17];
    const float* r_in_b   = (const float*)d_in[18];
    const float* r_out_w  = (const float*)d_in[19];
    const float* r_out_b  = (const float*)d_in[20];
    const float* r_ln1_g  = (const float*)d_in[21];
    const float* r_ln1_b  = (const float*)d_in[22];
    const float* r_ln2_g  = (const float*)d_in[23];
    const float* r_ln2_b  = (const float*)d_in[24];
    const float* r_w1     = (const float*)d_in[25];
    const float* r_b1     = (const float*)d_in[26];
    const float* r_w2     = (const float*)d_in[27];
    const float* r_b2     = (const float*)d_in[28];
    float* out = (float*)d_out;

    static int init_done = 0;
    static cudaStream_t s2;
    static cudaEvent_t ev_fork, ev_join, ev_q;
    if (!init_done) {
        cudaFuncSetAttribute(gemm_bf16_kernel,
                             cudaFuncAttributeMaxDynamicSharedMemorySize, 2*STGB);
        cudaStreamCreateWithFlags(&s2, cudaStreamNonBlocking);
        cudaEventCreateWithFlags(&ev_fork, cudaEventDisableTiming);
        cudaEventCreateWithFlags(&ev_join, cudaEventDisableTiming);
        cudaEventCreateWithFlags(&ev_q, cudaEventDisableTiming);
        init_done = 1;
    }

    float *p_part, *p_qkv, *p_seg1, *p_qh, *p_kv, *p_plan, *p_qkvr, *p_seg0;
    cudaGetSymbolAddress((void**)&p_part, g_part);
    cudaGetSymbolAddress((void**)&p_seg0, g_seg0);
    cudaGetSymbolAddress((void**)&p_qkv,  g_qkv);
    cudaGetSymbolAddress((void**)&p_seg1, g_seg1);
    cudaGetSymbolAddress((void**)&p_qh,   g_qh);
    cudaGetSymbolAddress((void**)&p_kv,   g_kv);
    cudaGetSymbolAddress((void**)&p_plan, g_plan);
    cudaGetSymbolAddress((void**)&p_qkvr, g_qkvr);

    __nv_bfloat16 *t_seg0, *t_o, *t_seg1, *t_wseg, *t_pq, *t_o2, *t_y, *t_o3, *t_ffn, *wbf;
    cudaGetSymbolAddress((void**)&t_seg0, g_bf_seg0);
    cudaGetSymbolAddress((void**)&t_o,    g_bf_o);
    cudaGetSymbolAddress((void**)&t_seg1, g_bf_seg1);
    cudaGetSymbolAddress((void**)&t_wseg, g_bf_wseg);
    cudaGetSymbolAddress((void**)&t_pq,   g_bf_pq);
    cudaGetSymbolAddress((void**)&t_o2,   g_bf_o2);
    cudaGetSymbolAddress((void**)&t_y,    g_bf_y);
    cudaGetSymbolAddress((void**)&t_o3,   g_bf_o3);
    cudaGetSymbolAddress((void**)&t_ffn,  g_bf_ffn);
    cudaGetSymbolAddress((void**)&wbf,    g_wbf);

    // 0) weight conversion + qh projection chain forked onto side stream
    CvtTab tab;
    tab.src[0]=sa_in_w;  tab.dst[0]=wbf+WOFF_SAIN;  tab.n[0]=3145728; tab.logK[0]=10;
    tab.src[1]=sa_out_w; tab.dst[1]=wbf+WOFF_SAOUT; tab.n[1]=1048576; tab.logK[1]=10;
    tab.src[2]=sal_w1;   tab.dst[2]=wbf+WOFF_SAL1;  tab.n[2]=1048576; tab.logK[2]=10;
    tab.src[3]=qa_in_w;  tab.dst[3]=wbf+WOFF_QAIN;  tab.n[3]=3145728; tab.logK[3]=10;
    tab.src[4]=qa_out_w; tab.dst[4]=wbf+WOFF_QAOUT; tab.n[4]=1048576; tab.logK[4]=10;
    tab.src[5]=r_in_w;   tab.dst[5]=wbf+WOFF_RIN;   tab.n[5]=6291456; tab.logK[5]=10;
    tab.src[6]=r_out_w;  tab.dst[6]=wbf+WOFF_ROUT;  tab.n[6]=2097152; tab.logK[6]=10;
    tab.src[7]=r_w1;     tab.dst[7]=wbf+WOFF_RW1;   tab.n[7]=8388608; tab.logK[7]=10;
    tab.src[8]=r_w2;     tab.dst[8]=wbf+WOFF_RW2;   tab.n[8]=8388608; tab.logK[8]=12;
    tab.src[9]=plan_q;   tab.dst[9]=t_pq;           tab.n[9]=6144;    tab.logK[9]=10;

    cudaEventRecord(ev_fork, 0);
    cudaStreamWaitEvent(s2, ev_fork, 0);
    convert_kernel<<<dim3(2048, 10), 256, 0, s2>>>(tab);
    cudaEventRecord(ev_join, s2);
    // qh projection: depends only on converted weights; own partial region (+7M)
    gemm(t_pq, wbf+WOFF_QAIN, NP, HH, HH, 32, p_part + 7*1024*1024, s2);
    epi(p_part + 7*1024*1024, qa_in_b, nullptr, p_qh, nullptr, 0, nullptr, NP, HH, 32, 0, s2);
    cudaEventRecord(ev_q, s2);

    // 1) fused segment pooling (computes lengths inline; overlaps convert)
    segpool_kernel<<<NB*NS, 256>>>(ts, mask);

    // join: GEMMs below need converted weights
    cudaStreamWaitEvent(0, ev_join, 0);

    // 2) segment self-attention
    gemm(t_seg0, wbf+WOFF_SAIN, 256, 3*HH, HH, 8, p_part);
    epi(p_part, sa_in_b, nullptr, p_qkv, nullptr, 0, nullptr, 256, 3*HH, 8, 0);
    attn_kernel<<<dim3(NB, NHEAD), 128>>>(p_qkv, p_qkv + HH, p_qkv + 2*HH, t_o,
                                          16, 16,
                                          3*HH, (long long)NS*3*HH,
                                          3*HH, (long long)NS*3*HH,
                                          3*HH, (long long)NS*3*HH);
    gemm(t_o, wbf+WOFF_SAOUT, 256, HH, HH, 16, p_part);
    epilogue_ln_kernel<<<256, 256>>>(p_part, sa_out_b, p_seg0, ln_g, ln_b,
                                     nullptr, p_seg1, t_seg1, 256, 16);

    // 3) salience (gelu-epilogue + logits fused)
    gemm(t_seg1, wbf+WOFF_SAL1, 256, HH, HH, 16, p_part);
    epilogue_logits_kernel<<<256, 256>>>(p_part, sal_b1, sal_w2, sal_b2, 256, 16);
    salience_kernel<<<16, 256>>>();

    // 4) plan cross-attention (qh computed on side stream)
    gemm(t_wseg, wbf+WOFF_QAIN + (size_t)HH*2*HH, 256, 2*HH, HH, 8, p_part);
    epi(p_part, qa_in_b + HH, nullptr, p_kv, nullptr, 0, nullptr, 256, 2*HH, 8, 0);
    cudaStreamWaitEvent(0, ev_q, 0);
    attn_kernel<<<dim3(NB, NHEAD), 128>>>(p_qh, p_kv, p_kv + HH, t_o2,
                                          NP, 16,
                                          HH,   0LL,
                                          2*HH, (long long)NS*2*HH,
                                          2*HH, (long long)NS*2*HH);
    gemm(t_o2, wbf+WOFF_QAOUT, NB*NP, HH, HH, 16, p_part);
    epilogue_ln_kernel<<<NB*NP, 256>>>(p_part, qa_out_b, nullptr, r_ln1_g, r_ln1_b,
                                       p_plan, nullptr, t_y, NB*NP, 16);

    // 5) refinement transformer layers (norm_first)
    for (int l = 0; l < 2; l++) {
        gemm(t_y, wbf+WOFF_RIN + (size_t)l*6291456, NB*NP, 3*HH, HH, 8, p_part);
        epi(p_part, r_in_b + l*3*HH, nullptr, p_qkvr, nullptr, 0, nullptr, NB*NP, 3*HH, 8, 0);
        attn_kernel<<<dim3(NB, NHEAD), 128>>>(p_qkvr, p_qkvr + HH, p_qkvr + 2*HH, t_o3,
                                              NP, NP,
                                              3*HH, (long long)NP*3*HH,
                                              3*HH, (long long)NP*3*HH,
                                              3*HH, (long long)NP*3*HH);
        gemm(t_o3, wbf+WOFF_ROUT + (size_t)l*2097152, NB*NP, HH, HH, 16, p_part);
        epilogue_ln_kernel<<<NB*NP, 256>>>(p_part, r_out_b + l*HH, p_plan,
                                           r_ln2_g + l*HH, r_ln2_b + l*HH,
                                           p_plan, nullptr, t_y, NB*NP, 16);
        gemm(t_y, wbf+WOFF_RW1 + (size_t)l*8388608, NB*NP, 4*HH, HH, 8, p_part);
        epi(p_part, r_b1 + l*4*HH, nullptr, nullptr, nullptr, 0, t_ffn, NB*NP, 4*HH, 8, 1);
        gemm(t_ffn, wbf+WOFF_RW2 + (size_t)l*8388608, NB*NP, HH, 4*HH, 32, p_part);
        if (l == 0) {
            epilogue_ln_kernel<<<NB*NP, 256>>>(p_part, r_b2, p_plan,
                                               r_ln1_g + HH, r_ln1_b + HH,
                                               p_plan, nullptr, t_y, NB*NP, 32);
        } else {
            int lim = out_size < PLAN_ELEMS ? out_size : PLAN_ELEMS;
            epi(p_part, r_b2 + HH, p_plan, p_plan, out, lim, nullptr, NB*NP, HH, 32, 0);
        }
    }

    // 6) redundancy + finalize (fused)
    red_kernel<<<16, 128>>>(out, out_size);
}